// round 8
// baseline (speedup 1.0000x reference)
#include <cuda_runtime.h>
#include <cuda_bf16.h>
#include <mma.h>
#include <math.h>
#include <stdint.h>

using namespace nvcuda;

#define T_STEPS 128
#define BATCH   512
#define HID     512
#define ADIM    18
#define ROWS    (T_STEPS * BATCH)   // 65536
#define NG3     (3 * HID)           // 1536
#define SC_CTAS 128
#define SC_GRP  32                  // CTAs per m-panel barrier group

// ---------------- scratch (static __device__, no allocs) ----------------
__device__ float g_S0[(size_t)ROWS * HID];
__device__ float g_S1[(size_t)ROWS * HID];
__device__ float g_Xg[(size_t)ROWS * NG3];
__device__ float g_h  [(size_t)BATCH * HID];   // fp32 carry (exact)
__device__ float g_htf[(size_t)BATCH * HID];   // tf32-RN shadow (GEMM A operand)
__device__ float g_w0c[HID * HID];
__device__ float g_w1c[HID * HID];
__device__ float g_wgc[HID * NG3];
__device__ unsigned int g_barg[4 * 32];        // per-group monotonic barriers (128B apart)

// ---------------- cp.async helpers ----------------
__device__ __forceinline__ void cp16(uint32_t dst, const void* src) {
    asm volatile("cp.async.cg.shared.global [%0], [%1], 16;" :: "r"(dst), "l"(src));
}
#define CP_COMMIT() asm volatile("cp.async.commit_group;")
#define CP_WAIT0()  asm volatile("cp.async.wait_group 0;")
#define CP_WAIT1()  asm volatile("cp.async.wait_group 1;")

__device__ __forceinline__ float tf32r(float x) { return wmma::__float_to_tf32(x); }

__device__ __forceinline__ float tanh_apx(float x) {
    float y; asm("tanh.approx.f32 %0, %1;" : "=f"(y) : "f"(x)); return y;
}
__device__ __forceinline__ float sigm_apx(float x) { return 0.5f * tanh_apx(0.5f * x) + 0.5f; }

// ---------------- tf32-RN conversion passes ----------------
__global__ void conv_tf32(const float* __restrict__ s, float* __restrict__ d, int n4) {
    int i = blockIdx.x * 256 + threadIdx.x;
    if (i < n4) {
        float4 v = ((const float4*)s)[i];
        v.x = tf32r(v.x); v.y = tf32r(v.y); v.z = tf32r(v.z); v.w = tf32r(v.w);
        ((float4*)d)[i] = v;
    }
}

// interleave [w_ir | w_iz | w_in] column-wise into [512,1536] tf32
__global__ void conv_gates(const float* __restrict__ wir, const float* __restrict__ wiz,
                           const float* __restrict__ win, float* __restrict__ dst) {
    int i = blockIdx.x * 256 + threadIdx.x;   // 262144
    int k = i >> 9, c = i & 511;
    size_t o = (size_t)k * NG3 + c;
    dst[o]        = tf32r(wir[i]);
    dst[o + 512]  = tf32r(wiz[i]);
    dst[o + 1024] = tf32r(win[i]);
}

// ---------------- 3-stage TF32 GEMM: BM=128 BN=128 BK=32 ----------------
#define GA_LD 36
#define GB_LD 132
#define GA_SZ (128 * GA_LD)
#define GB_SZ (32 * GB_LD)

__global__ void __launch_bounds__(256, 2) gemm_db(
    const float* __restrict__ A, const float* __restrict__ B,
    float* __restrict__ C, int N, int K)
{
    extern __shared__ float sm[];
    float* As = sm;
    float* Bs = sm + 3 * GA_SZ;

    const int tid = threadIdx.x;
    const int wid = tid >> 5;
    const size_t m0 = (size_t)blockIdx.y * 128;
    const int n0 = blockIdx.x * 128;
    const int wm = (wid >> 2) * 64;
    const int wn = (wid & 3) * 32;

    wmma::fragment<wmma::accumulator, 16, 16, 8, float> acc[4][2];
#pragma unroll
    for (int i = 0; i < 4; i++)
#pragma unroll
        for (int j = 0; j < 2; j++) wmma::fill_fragment(acc[i][j], 0.0f);

    const int NK = K / 32;

    auto load_stage = [&](int kc, int buf) {
        int k0 = kc * 32;
#pragma unroll
        for (int l = 0; l < 4; l++) {
            int f = tid + l * 256;
            int r = f >> 3, c = (f & 7) * 4;
            cp16((uint32_t)__cvta_generic_to_shared(As + buf * GA_SZ + r * GA_LD + c),
                 A + (m0 + r) * (size_t)K + k0 + c);
        }
#pragma unroll
        for (int l = 0; l < 4; l++) {
            int f = tid + l * 256;
            int r = f >> 5, c = (f & 31) * 4;
            cp16((uint32_t)__cvta_generic_to_shared(Bs + buf * GB_SZ + r * GB_LD + c),
                 B + (size_t)(k0 + r) * N + n0 + c);
        }
    };

    load_stage(0, 0); CP_COMMIT();
    load_stage(1, 1); CP_COMMIT();

    for (int kc = 0; kc < NK; kc++) {
        int buf = kc % 3;
        if (kc + 1 < NK) CP_WAIT1(); else CP_WAIT0();
        __syncthreads();
        if (kc + 2 < NK) { load_stage(kc + 2, (kc + 2) % 3); CP_COMMIT(); }
#pragma unroll
        for (int kk = 0; kk < 32; kk += 8) {
            wmma::fragment<wmma::matrix_a, 16, 16, 8, wmma::precision::tf32, wmma::row_major> af[4];
            wmma::fragment<wmma::matrix_b, 16, 16, 8, wmma::precision::tf32, wmma::row_major> bf[2];
#pragma unroll
            for (int i = 0; i < 4; i++)
                wmma::load_matrix_sync(af[i], As + buf * GA_SZ + (wm + 16 * i) * GA_LD + kk, GA_LD);
#pragma unroll
            for (int j = 0; j < 2; j++)
                wmma::load_matrix_sync(bf[j], Bs + buf * GB_SZ + kk * GB_LD + wn + 16 * j, GB_LD);
#pragma unroll
            for (int i = 0; i < 4; i++)
#pragma unroll
                for (int j = 0; j < 2; j++) wmma::mma_sync(acc[i][j], af[i], bf[j], acc[i][j]);
        }
    }
    __syncthreads();
#pragma unroll
    for (int i = 0; i < 4; i++)
#pragma unroll
        for (int j = 0; j < 2; j++)
            wmma::store_matrix_sync(C + (m0 + wm + 16 * i) * (size_t)N + n0 + wn + 16 * j,
                                    acc[i][j], N, wmma::mem_row_major);
}

// ---------------- LayerNorm(+bias,+one-hot) + ReLU, tf32-RN output ----------------
__global__ void __launch_bounds__(128) ln_relu_kernel(
    const float* __restrict__ in, float* __restrict__ out,
    const float* __restrict__ addb,
    const float* __restrict__ lns, const float* __restrict__ lnb,
    const float* __restrict__ w_oh, const int* __restrict__ acts)
{
    const int row = blockIdx.x;
    const int tid = threadIdx.x;
    const float* ip = in + (size_t)row * HID;

    float4 v = *(const float4*)(ip + tid * 4);
    float4 a = *(const float4*)(addb + tid * 4);
    v.x += a.x; v.y += a.y; v.z += a.z; v.w += a.w;
    if (w_oh) {
        const float* oh = w_oh + (size_t)(512 + acts[row]) * HID;
        float4 o = *(const float4*)(oh + tid * 4);
        v.x += o.x; v.y += o.y; v.z += o.z; v.w += o.w;
    }
    float sum = v.x + v.y + v.z + v.w;
    float sq  = v.x * v.x + v.y * v.y + v.z * v.z + v.w * v.w;

    __shared__ float red[8];
#pragma unroll
    for (int off = 16; off > 0; off >>= 1) {
        sum += __shfl_down_sync(0xFFFFFFFFu, sum, off);
        sq  += __shfl_down_sync(0xFFFFFFFFu, sq,  off);
    }
    if ((tid & 31) == 0) { red[tid >> 5] = sum; red[4 + (tid >> 5)] = sq; }
    __syncthreads();
    float ts = red[0] + red[1] + red[2] + red[3];
    float tq = red[4] + red[5] + red[6] + red[7];
    float mean = ts * (1.0f / HID);
    float var  = tq * (1.0f / HID) - mean * mean;
    float inv  = rsqrtf(var + 1e-6f);

    float4 sc = *(const float4*)(lns + tid * 4);
    float4 bb = *(const float4*)(lnb + tid * 4);
    float4 r;
    r.x = tf32r(fmaxf((v.x - mean) * inv * sc.x + bb.x, 0.0f));
    r.y = tf32r(fmaxf((v.y - mean) * inv * sc.y + bb.y, 0.0f));
    r.z = tf32r(fmaxf((v.z - mean) * inv * sc.z + bb.z, 0.0f));
    r.w = tf32r(fmaxf((v.w - mean) * inv * sc.w + bb.w, 0.0f));
    *(float4*)(out + (size_t)row * HID + tid * 4) = r;
}

// ---------------- initial done-mask ----------------
__global__ void mask0_kernel(const float* __restrict__ hidden_in,
                             const int* __restrict__ dones)
{
    int i = blockIdx.x * blockDim.x + threadIdx.x;
    int b = i >> 9;
    float v = dones[b] ? 0.0f : hidden_in[i];
    g_h[i] = v;
    g_htf[i] = tf32r(v);
}

// ---------------- persistent fused GRU scan v3 ----------------
// 128 CTAs x 512 thr.  bx: c0 = (bx&31)*16, m-panel = bx>>5 (4 groups of 32 CTAs).
// Warps 0-7: r+z accs for m-slab wid; warps 8-15: n acc for m-slab wid-8.
// Barrier is per-32-CTA m-panel group (groups share only their own h rows).
__device__ __forceinline__ void gsync_grp(int grp) {
    __threadfence();
    __syncthreads();
    if (threadIdx.x == 0) {
        unsigned int* ctr = &g_barg[grp * 32];
        unsigned int old = atomicAdd(ctr, 1u);
        unsigned int target = (old / SC_GRP + 1u) * SC_GRP;
        while (*((volatile unsigned int*)ctr) < target) { }
        __threadfence();
    }
    __syncthreads();
}

#define SA_LD 36
#define SA_SZ (128 * SA_LD)

__global__ void __launch_bounds__(512, 1) scan_kernel(
    const float* __restrict__ w_hr, const float* __restrict__ w_hz, const float* __restrict__ w_hn,
    const float* __restrict__ b_ir, const float* __restrict__ b_iz,
    const float* __restrict__ b_in, const float* __restrict__ b_hn,
    const int* __restrict__ dones,
    float* __restrict__ out_hidden)
{
    extern __shared__ float ssm[];
    float* Wp = ssm;                      // 3 * 512 * 20
    float* At = Wp + 3 * 512 * 20;        // 3 * SA_SZ
    float* Sc = At + 3 * SA_SZ;           // 128 * 52
    float* Bb = Sc + 128 * 52;            // 64

    const int tid  = threadIdx.x;
    const int wid  = tid >> 5;
    const int bx   = blockIdx.x;
    const int c0   = (bx & 31) * 16;
    const int grp  = bx >> 5;
    const int m0   = grp * 128;

    // prologue: weight panels [512 x 16] x3 as tf32-RN + bias slices
    {
        const float* Ws[3] = {w_hr, w_hz, w_hn};
#pragma unroll
        for (int g = 0; g < 3; g++) {
            for (int i4 = tid; i4 < 2048; i4 += 512) {
                int k = i4 >> 2, cc = (i4 & 3) * 4;
                float4 v = *(const float4*)(Ws[g] + (size_t)k * HID + c0 + cc);
                float* d = Wp + g * (512 * 20) + k * 20 + cc;
                d[0] = tf32r(v.x); d[1] = tf32r(v.y); d[2] = tf32r(v.z); d[3] = tf32r(v.w);
            }
        }
        if (tid < 16) {
            Bb[tid]      = b_ir[c0 + tid];
            Bb[16 + tid] = b_iz[c0 + tid];
            Bb[32 + tid] = b_in[c0 + tid];
            Bb[48 + tid] = b_hn[c0 + tid];
        }
    }
    __syncthreads();

    const bool isRZ = (wid < 8);
    const int wrow = (isRZ ? wid : wid - 8) * 16;

    auto load_chunk = [&](int k0, int buf) {
#pragma unroll
        for (int l = 0; l < 2; l++) {
            int f = tid + l * 512;
            int r = f >> 3, c = (f & 7) * 4;
            cp16((uint32_t)__cvta_generic_to_shared(At + buf * SA_SZ + r * SA_LD + c),
                 g_htf + (size_t)(m0 + r) * HID + k0 + c);
        }
    };

    // gates element mapping: thread owns 4 consecutive cols of one row
    const int grow = tid >> 2;            // 0..127
    const int gcol4 = (tid & 3) * 4;      // 0,4,8,12
    const int bg = m0 + grow;
    const int cg0 = c0 + gcol4;
    const float4 bir = *(const float4*)(Bb + gcol4);
    // NOTE: Bb biases read after __syncthreads above; reload per use below to keep regs low.

    for (int t = 0; t < T_STEPS; t++) {
        const bool lastt = (t == T_STEPS - 1);

        // ---- prefetch step inputs (latency hidden under GEMM) ----
        const float* xg = g_Xg + ((size_t)t * BATCH + bg) * NG3 + cg0;
        float4 pxr = __ldcg((const float4*)xg);
        float4 pxz = __ldcg((const float4*)(xg + 512));
        float4 pxn = __ldcg((const float4*)(xg + 1024));
        float4 ph  = *(const float4*)(g_h + (size_t)bg * HID + cg0);
        int pdn = lastt ? 0 : dones[(t + 1) * BATCH + bg];

        // ---- GEMM: Hg_local[128 x 48] = htf[m0:,:] @ Wp (3-stage, 16 warps) ----
        wmma::fragment<wmma::accumulator, 16, 16, 8, float> accA, accB;
        wmma::fill_fragment(accA, 0.0f);
        wmma::fill_fragment(accB, 0.0f);

        load_chunk(0, 0); CP_COMMIT();
        load_chunk(32, 1); CP_COMMIT();

        for (int kc = 0; kc < 16; kc++) {
            int buf = kc % 3;
            if (kc + 1 < 16) CP_WAIT1(); else CP_WAIT0();
            __syncthreads();
            if (kc + 2 < 16) { load_chunk((kc + 2) * 32, (kc + 2) % 3); CP_COMMIT(); }
            int k0 = kc * 32;
#pragma unroll
            for (int kk = 0; kk < 32; kk += 8) {
                wmma::fragment<wmma::matrix_a, 16, 16, 8, wmma::precision::tf32, wmma::row_major> af;
                wmma::load_matrix_sync(af, At + buf * SA_SZ + wrow * SA_LD + kk, SA_LD);
                if (isRZ) {
                    wmma::fragment<wmma::matrix_b, 16, 16, 8, wmma::precision::tf32, wmma::row_major> bfr, bfz;
                    wmma::load_matrix_sync(bfr, Wp + 0 * (512 * 20) + (k0 + kk) * 20, 20);
                    wmma::load_matrix_sync(bfz, Wp + 1 * (512 * 20) + (k0 + kk) * 20, 20);
                    wmma::mma_sync(accA, af, bfr, accA);
                    wmma::mma_sync(accB, af, bfz, accB);
                } else {
                    wmma::fragment<wmma::matrix_b, 16, 16, 8, wmma::precision::tf32, wmma::row_major> bfn;
                    wmma::load_matrix_sync(bfn, Wp + 2 * (512 * 20) + (k0 + kk) * 20, 20);
                    wmma::mma_sync(accA, af, bfn, accA);
                }
            }
        }

        // spill accs: r -> col 0, z -> col 16 (RZ warps); n -> col 32 (N warps)
        if (isRZ) {
            wmma::store_matrix_sync(Sc + wrow * 52 + 0,  accA, 52, wmma::mem_row_major);
            wmma::store_matrix_sync(Sc + wrow * 52 + 16, accB, 52, wmma::mem_row_major);
        } else {
            wmma::store_matrix_sync(Sc + wrow * 52 + 32, accA, 52, wmma::mem_row_major);
        }
        __syncthreads();   // gates read r/z/n produced by different warps

        // ---- gates: 4 elems/thread, float4 ----
        {
            float4 hgr = *(const float4*)(Sc + grow * 52 + gcol4);
            float4 hgz = *(const float4*)(Sc + grow * 52 + 16 + gcol4);
            float4 hgn = *(const float4*)(Sc + grow * 52 + 32 + gcol4);
            float4 biz = *(const float4*)(Bb + 16 + gcol4);
            float4 bin = *(const float4*)(Bb + 32 + gcol4);
            float4 bhn = *(const float4*)(Bb + 48 + gcol4);

            float4 hn4, hm4;
            {
                float r0 = sigm_apx(pxr.x + bir.x + hgr.x);
                float z0 = sigm_apx(pxz.x + biz.x + hgz.x);
                float n0 = tanh_apx(pxn.x + bin.x + r0 * (hgn.x + bhn.x));
                hn4.x = (1.0f - z0) * n0 + z0 * ph.x;
                float r1 = sigm_apx(pxr.y + bir.y + hgr.y);
                float z1 = sigm_apx(pxz.y + biz.y + hgz.y);
                float n1 = tanh_apx(pxn.y + bin.y + r1 * (hgn.y + bhn.y));
                hn4.y = (1.0f - z1) * n1 + z1 * ph.y;
                float r2 = sigm_apx(pxr.z + bir.z + hgr.z);
                float z2 = sigm_apx(pxz.z + biz.z + hgz.z);
                float n2 = tanh_apx(pxn.z + bin.z + r2 * (hgn.z + bhn.z));
                hn4.z = (1.0f - z2) * n2 + z2 * ph.z;
                float r3 = sigm_apx(pxr.w + bir.w + hgr.w);
                float z3 = sigm_apx(pxz.w + biz.w + hgz.w);
                float n3 = tanh_apx(pxn.w + bin.w + r3 * (hgn.w + bhn.w));
                hn4.w = (1.0f - z3) * n3 + z3 * ph.w;
            }
            *(float4*)(g_S0 + ((size_t)t * BATCH + bg) * HID + cg0) = hn4;
            if (pdn) { hm4 = make_float4(0.f, 0.f, 0.f, 0.f); } else { hm4 = hn4; }
            size_t hi = (size_t)bg * HID + cg0;
            *(float4*)(g_h + hi) = hm4;
            float4 ht = make_float4(tf32r(hm4.x), tf32r(hm4.y), tf32r(hm4.z), tf32r(hm4.w));
            *(float4*)(g_htf + hi) = ht;
            if (lastt) *(float4*)(out_hidden + hi) = hn4;
        }

        if (!lastt) gsync_grp(grp);
    }
}

// ---------------- output head ----------------
__global__ void __launch_bounds__(256) qout_kernel(
    const float* __restrict__ w_out, const float* __restrict__ b_out,
    float* __restrict__ q)
{
    __shared__ float ws[HID * ADIM];
    for (int i = threadIdx.x; i < HID * ADIM; i += 256) ws[i] = w_out[i];
    __syncthreads();

    const size_t row = (size_t)blockIdx.x * 256 + threadIdx.x;
    const float* y = g_S0 + row * HID;
    float acc[ADIM];
#pragma unroll
    for (int a = 0; a < ADIM; a++) acc[a] = b_out[a];

    for (int c = 0; c < HID; c += 4) {
        float4 v = *(const float4*)(y + c);
        float yv[4] = {v.x, v.y, v.z, v.w};
#pragma unroll
        for (int j = 0; j < 4; j++)
#pragma unroll
            for (int a = 0; a < ADIM; a++)
                acc[a] = fmaf(yv[j], ws[(c + j) * ADIM + a], acc[a]);
    }
    float* qp = q + row * ADIM;
#pragma unroll
    for (int a = 0; a < ADIM; a++) qp[a] = acc[a];
}

// ---------------- launch ----------------
extern "C" void kernel_launch(void* const* d_in, const int* in_sizes, int n_in,
                              void* d_out, int out_size)
{
    const float* hidden    = (const float*)d_in[0];
    const float* obs       = (const float*)d_in[1];
    const int*   dones     = (const int*)d_in[2];
    const int*   last_acts = (const int*)d_in[3];
    const float* w0   = (const float*)d_in[4];
    const float* b0   = (const float*)d_in[5];
    const float* ln0s = (const float*)d_in[6];
    const float* ln0b = (const float*)d_in[7];
    const float* w1   = (const float*)d_in[8];
    const float* b1   = (const float*)d_in[9];
    const float* ln1s = (const float*)d_in[10];
    const float* ln1b = (const float*)d_in[11];
    const float* w_ir = (const float*)d_in[12];
    const float* b_ir = (const float*)d_in[13];
    const float* w_iz = (const float*)d_in[14];
    const float* b_iz = (const float*)d_in[15];
    const float* w_in = (const float*)d_in[16];
    const float* b_in = (const float*)d_in[17];
    const float* w_hr = (const float*)d_in[18];
    const float* w_hz = (const float*)d_in[19];
    const float* w_hn = (const float*)d_in[20];
    const float* b_hn = (const float*)d_in[21];
    const float* w_out = (const float*)d_in[22];
    const float* b_out = (const float*)d_in[23];

    float* out_hidden = (float*)d_out;
    float* out_q      = (float*)d_out + (size_t)BATCH * HID;

    float *S0, *S1, *Xg, *w0c, *w1c, *wgc;
    cudaGetSymbolAddress((void**)&S0,  g_S0);
    cudaGetSymbolAddress((void**)&S1,  g_S1);
    cudaGetSymbolAddress((void**)&Xg,  g_Xg);
    cudaGetSymbolAddress((void**)&w0c, g_w0c);
    cudaGetSymbolAddress((void**)&w1c, g_w1c);
    cudaGetSymbolAddress((void**)&wgc, g_wgc);

    const int gemm_smem = 3 * (GA_SZ + GB_SZ) * 4;                              // 105984 B
    const int scan_smem = (3 * 512 * 20 + 3 * SA_SZ + 128 * 52 + 64) * 4;       // 205056 B
    cudaFuncSetAttribute(gemm_db, cudaFuncAttributeMaxDynamicSharedMemorySize, gemm_smem);
    cudaFuncSetAttribute(scan_kernel, cudaFuncAttributeMaxDynamicSharedMemorySize, scan_smem);

    conv_tf32<<<(ROWS * HID / 4 + 255) / 256, 256>>>(obs, S1, ROWS * HID / 4);
    conv_tf32<<<256, 256>>>(w0, w0c, HID * HID / 4);
    conv_gates<<<1024, 256>>>(w_ir, w_iz, w_in, wgc);
    gemm_db<<<dim3(4, 512), 256, gemm_smem>>>(S1, w0c, S0, HID, HID);     // L0
    conv_tf32<<<256, 256>>>(w1, w1c, HID * HID / 4);
    mask0_kernel<<<(BATCH * HID) / 256, 256>>>(hidden, dones);
    ln_relu_kernel<<<ROWS, 128>>>(S0, S1, b0, ln0s, ln0b, w0, last_acts);
    gemm_db<<<dim3(4, 512), 256, gemm_smem>>>(S1, w1c, S0, HID, HID);     // L1
    ln_relu_kernel<<<ROWS, 128>>>(S0, S1, b1, ln1s, ln1b, nullptr, nullptr);
    gemm_db<<<dim3(12, 512), 256, gemm_smem>>>(S1, wgc, Xg, NG3, HID);    // gates

    scan_kernel<<<SC_CTAS, 512, scan_smem>>>(w_hr, w_hz, w_hn,
                                             b_ir, b_iz, b_in, b_hn,
                                             dones, out_hidden);

    qout_kernel<<<ROWS / 256, 256>>>(w_out, b_out, out_q);
}

// round 10
// speedup vs baseline: 1.1285x; 1.1285x over previous
#include <cuda_runtime.h>
#include <cuda_bf16.h>
#include <mma.h>
#include <math.h>
#include <stdint.h>

using namespace nvcuda;

#define T_STEPS 128
#define BATCH   512
#define HID     512
#define ADIM    18
#define ROWS    (T_STEPS * BATCH)   // 65536
#define NG3     (3 * HID)           // 1536
#define SC_CTAS 128

// ---------------- scratch (static __device__, no allocs) ----------------
__device__ float g_S0[(size_t)ROWS * HID];
__device__ float g_S1[(size_t)ROWS * HID];
__device__ float g_Xg[(size_t)ROWS * NG3];
__device__ float g_h  [(size_t)BATCH * HID];   // fp32 carry (exact)
__device__ float g_htf[(size_t)BATCH * HID];   // tf32-RN shadow (GEMM A operand)
__device__ float g_w0c[HID * HID];
__device__ float g_w1c[HID * HID];
__device__ float g_wgc[HID * NG3];
__device__ unsigned int g_bar;                 // monotonic grid barrier

// ---------------- cp.async helpers ----------------
__device__ __forceinline__ void cp16(uint32_t dst, const void* src) {
    asm volatile("cp.async.cg.shared.global [%0], [%1], 16;" :: "r"(dst), "l"(src));
}
#define CP_COMMIT() asm volatile("cp.async.commit_group;")
#define CP_WAIT0()  asm volatile("cp.async.wait_group 0;")
#define CP_WAIT1()  asm volatile("cp.async.wait_group 1;")

__device__ __forceinline__ float tf32r(float x) { return wmma::__float_to_tf32(x); }

__device__ __forceinline__ float tanh_apx(float x) {
    float y; asm("tanh.approx.f32 %0, %1;" : "=f"(y) : "f"(x)); return y;
}
__device__ __forceinline__ float sigm_apx(float x) { return 0.5f * tanh_apx(0.5f * x) + 0.5f; }

// ---------------- tf32-RN conversion passes ----------------
__global__ void conv_tf32(const float* __restrict__ s, float* __restrict__ d, int n4) {
    int i = blockIdx.x * 256 + threadIdx.x;
    if (i < n4) {
        float4 v = ((const float4*)s)[i];
        v.x = tf32r(v.x); v.y = tf32r(v.y); v.z = tf32r(v.z); v.w = tf32r(v.w);
        ((float4*)d)[i] = v;
    }
}

// interleave [w_ir | w_iz | w_in] column-wise into [512,1536] tf32
__global__ void conv_gates(const float* __restrict__ wir, const float* __restrict__ wiz,
                           const float* __restrict__ win, float* __restrict__ dst) {
    int i = blockIdx.x * 256 + threadIdx.x;   // 262144
    int k = i >> 9, c = i & 511;
    size_t o = (size_t)k * NG3 + c;
    dst[o]        = tf32r(wir[i]);
    dst[o + 512]  = tf32r(wiz[i]);
    dst[o + 1024] = tf32r(win[i]);
}

// ---------------- 3-stage TF32 GEMM: BM=128 BN=128 BK=32, 4 warps, 64x64 warp tile ----
#define GA_LD 36
#define GB_LD 132
#define GA_SZ (128 * GA_LD)
#define GB_SZ (32 * GB_LD)

__global__ void __launch_bounds__(128, 2) gemm_db(
    const float* __restrict__ A, const float* __restrict__ B,
    float* __restrict__ C, int N, int K)
{
    extern __shared__ float sm[];
    float* As = sm;
    float* Bs = sm + 3 * GA_SZ;

    const int tid = threadIdx.x;
    const int wid = tid >> 5;
    const size_t m0 = (size_t)blockIdx.y * 128;
    const int n0 = blockIdx.x * 128;
    const int wm = (wid >> 1) * 64;    // 2x2 warp grid, 64x64 per warp
    const int wn = (wid & 1) * 64;

    wmma::fragment<wmma::accumulator, 16, 16, 8, float> acc[4][4];
#pragma unroll
    for (int i = 0; i < 4; i++)
#pragma unroll
        for (int j = 0; j < 4; j++) wmma::fill_fragment(acc[i][j], 0.0f);

    const int NK = K / 32;

    // A: 128x32 = 1024 float4, 8/thread.  B: 32x128 = 1024 float4, 8/thread.
    auto load_stage = [&](int kc, int buf) {
        int k0 = kc * 32;
#pragma unroll
        for (int l = 0; l < 8; l++) {
            int f = tid + l * 128;
            int r = f >> 3, c = (f & 7) * 4;
            cp16((uint32_t)__cvta_generic_to_shared(As + buf * GA_SZ + r * GA_LD + c),
                 A + (m0 + r) * (size_t)K + k0 + c);
        }
#pragma unroll
        for (int l = 0; l < 8; l++) {
            int f = tid + l * 128;
            int r = f >> 5, c = (f & 31) * 4;
            cp16((uint32_t)__cvta_generic_to_shared(Bs + buf * GB_SZ + r * GB_LD + c),
                 B + (size_t)(k0 + r) * N + n0 + c);
        }
    };

    load_stage(0, 0); CP_COMMIT();
    load_stage(1, 1); CP_COMMIT();

    for (int kc = 0; kc < NK; kc++) {
        int buf = kc % 3;
        if (kc + 1 < NK) CP_WAIT1(); else CP_WAIT0();
        __syncthreads();
        if (kc + 2 < NK) { load_stage(kc + 2, (kc + 2) % 3); CP_COMMIT(); }
#pragma unroll
        for (int kk = 0; kk < 32; kk += 8) {
            wmma::fragment<wmma::matrix_a, 16, 16, 8, wmma::precision::tf32, wmma::row_major> af[4];
            wmma::fragment<wmma::matrix_b, 16, 16, 8, wmma::precision::tf32, wmma::row_major> bf[4];
#pragma unroll
            for (int i = 0; i < 4; i++)
                wmma::load_matrix_sync(af[i], As + buf * GA_SZ + (wm + 16 * i) * GA_LD + kk, GA_LD);
#pragma unroll
            for (int j = 0; j < 4; j++)
                wmma::load_matrix_sync(bf[j], Bs + buf * GB_SZ + kk * GB_LD + wn + 16 * j, GB_LD);
#pragma unroll
            for (int i = 0; i < 4; i++)
#pragma unroll
                for (int j = 0; j < 4; j++) wmma::mma_sync(acc[i][j], af[i], bf[j], acc[i][j]);
        }
    }
    __syncthreads();
#pragma unroll
    for (int i = 0; i < 4; i++)
#pragma unroll
        for (int j = 0; j < 4; j++)
            wmma::store_matrix_sync(C + (m0 + wm + 16 * i) * (size_t)N + n0 + wn + 16 * j,
                                    acc[i][j], N, wmma::mem_row_major);
}

// ---------------- LayerNorm(+bias,+one-hot) + ReLU, tf32-RN output ----------------
__global__ void __launch_bounds__(128) ln_relu_kernel(
    const float* __restrict__ in, float* __restrict__ out,
    const float* __restrict__ addb,
    const float* __restrict__ lns, const float* __restrict__ lnb,
    const float* __restrict__ w_oh, const int* __restrict__ acts)
{
    const int row = blockIdx.x;
    const int tid = threadIdx.x;
    const float* ip = in + (size_t)row * HID;

    float4 v = *(const float4*)(ip + tid * 4);
    float4 a = *(const float4*)(addb + tid * 4);
    v.x += a.x; v.y += a.y; v.z += a.z; v.w += a.w;
    if (w_oh) {
        const float* oh = w_oh + (size_t)(512 + acts[row]) * HID;
        float4 o = *(const float4*)(oh + tid * 4);
        v.x += o.x; v.y += o.y; v.z += o.z; v.w += o.w;
    }
    float sum = v.x + v.y + v.z + v.w;
    float sq  = v.x * v.x + v.y * v.y + v.z * v.z + v.w * v.w;

    __shared__ float red[8];
#pragma unroll
    for (int off = 16; off > 0; off >>= 1) {
        sum += __shfl_down_sync(0xFFFFFFFFu, sum, off);
        sq  += __shfl_down_sync(0xFFFFFFFFu, sq,  off);
    }
    if ((tid & 31) == 0) { red[tid >> 5] = sum; red[4 + (tid >> 5)] = sq; }
    __syncthreads();
    float ts = red[0] + red[1] + red[2] + red[3];
    float tq = red[4] + red[5] + red[6] + red[7];
    float mean = ts * (1.0f / HID);
    float var  = tq * (1.0f / HID) - mean * mean;
    float inv  = rsqrtf(var + 1e-6f);

    float4 sc = *(const float4*)(lns + tid * 4);
    float4 bb = *(const float4*)(lnb + tid * 4);
    float4 r;
    r.x = tf32r(fmaxf((v.x - mean) * inv * sc.x + bb.x, 0.0f));
    r.y = tf32r(fmaxf((v.y - mean) * inv * sc.y + bb.y, 0.0f));
    r.z = tf32r(fmaxf((v.z - mean) * inv * sc.z + bb.z, 0.0f));
    r.w = tf32r(fmaxf((v.w - mean) * inv * sc.w + bb.w, 0.0f));
    *(float4*)(out + (size_t)row * HID + tid * 4) = r;
}

// ---------------- initial done-mask ----------------
__global__ void mask0_kernel(const float* __restrict__ hidden_in,
                             const int* __restrict__ dones)
{
    int i = blockIdx.x * blockDim.x + threadIdx.x;
    int b = i >> 9;
    float v = dones[b] ? 0.0f : hidden_in[i];
    g_h[i] = v;
    g_htf[i] = tf32r(v);
}

// ---------------- persistent fused GRU scan (R6 structure, tanh_apx n-gate) ----------------
__device__ __forceinline__ void gsync() {
    __threadfence();
    __syncthreads();
    if (threadIdx.x == 0) {
        unsigned int old = atomicAdd(&g_bar, 1u);
        unsigned int target = (old / SC_CTAS + 1u) * SC_CTAS;
        while (*((volatile unsigned int*)&g_bar) < target) { }
        __threadfence();
    }
    __syncthreads();
}

#define SA_LD 36
#define SA_SZ (128 * SA_LD)

__global__ void __launch_bounds__(256, 1) scan_kernel(
    const float* __restrict__ w_hr, const float* __restrict__ w_hz, const float* __restrict__ w_hn,
    const float* __restrict__ b_ir, const float* __restrict__ b_iz,
    const float* __restrict__ b_in, const float* __restrict__ b_hn,
    const int* __restrict__ dones,
    float* __restrict__ out_hidden)
{
    extern __shared__ float ssm[];
    float* Wp = ssm;
    float* At = Wp + 3 * 512 * 20;
    float* Sc = At + 3 * SA_SZ;
    float* Bb = Sc + 128 * 52;

    const int tid  = threadIdx.x;
    const int wid  = tid >> 5;
    const int lane = tid & 31;
    const int bx   = blockIdx.x;
    const int c0   = (bx & 31) * 16;
    const int m0   = (bx >> 5) * 128;

    {
        const float* Ws[3] = {w_hr, w_hz, w_hn};
#pragma unroll
        for (int g = 0; g < 3; g++) {
            for (int i4 = tid; i4 < 2048; i4 += 256) {
                int k = i4 >> 2, cc = (i4 & 3) * 4;
                float4 v = *(const float4*)(Ws[g] + (size_t)k * HID + c0 + cc);
                float* d = Wp + g * (512 * 20) + k * 20 + cc;
                d[0] = tf32r(v.x); d[1] = tf32r(v.y); d[2] = tf32r(v.z); d[3] = tf32r(v.w);
            }
        }
        if (tid < 16) {
            Bb[tid]      = b_ir[c0 + tid];
            Bb[16 + tid] = b_iz[c0 + tid];
            Bb[32 + tid] = b_in[c0 + tid];
            Bb[48 + tid] = b_hn[c0 + tid];
        }
    }
    __syncthreads();

    const int wrow = wid * 16;

    auto load_chunk = [&](int k0, int buf) {
#pragma unroll
        for (int l = 0; l < 4; l++) {
            int f = tid + l * 256;
            int r = f >> 3, c = (f & 7) * 4;
            cp16((uint32_t)__cvta_generic_to_shared(At + buf * SA_SZ + r * SA_LD + c),
                 g_htf + (size_t)(m0 + r) * HID + k0 + c);
        }
    };

    int erow[8], ecol[8];
#pragma unroll
    for (int j = 0; j < 8; j++) { int e = j * 32 + lane; erow[j] = e >> 4; ecol[j] = e & 15; }

    for (int t = 0; t < T_STEPS; t++) {
        const bool lastt = (t == T_STEPS - 1);

        // prefetch step inputs (latency hidden under GEMM)
        float pxr[8], pxz[8], pxn[8], ph[8];
        int pdn[8];
#pragma unroll
        for (int j = 0; j < 8; j++) {
            int bg = m0 + wrow + erow[j];
            int cg = c0 + ecol[j];
            const float* xg = g_Xg + ((size_t)t * BATCH + bg) * NG3 + cg;
            pxr[j] = __ldcg(xg);
            pxz[j] = __ldcg(xg + 512);
            pxn[j] = __ldcg(xg + 1024);
            ph[j]  = g_h[(size_t)bg * HID + cg];
            pdn[j] = lastt ? 0 : dones[(t + 1) * BATCH + bg];
        }

        wmma::fragment<wmma::accumulator, 16, 16, 8, float> acc[3];
#pragma unroll
        for (int g = 0; g < 3; g++) wmma::fill_fragment(acc[g], 0.0f);

        load_chunk(0, 0); CP_COMMIT();
        load_chunk(32, 1); CP_COMMIT();

        for (int kc = 0; kc < 16; kc++) {
            int buf = kc % 3;
            if (kc + 1 < 16) CP_WAIT1(); else CP_WAIT0();
            __syncthreads();
            if (kc + 2 < 16) { load_chunk((kc + 2) * 32, (kc + 2) % 3); CP_COMMIT(); }
            int k0 = kc * 32;
#pragma unroll
            for (int kk = 0; kk < 32; kk += 8) {
                wmma::fragment<wmma::matrix_a, 16, 16, 8, wmma::precision::tf32, wmma::row_major> af;
                wmma::load_matrix_sync(af, At + buf * SA_SZ + wrow * SA_LD + kk, SA_LD);
#pragma unroll
                for (int g = 0; g < 3; g++) {
                    wmma::fragment<wmma::matrix_b, 16, 16, 8, wmma::precision::tf32, wmma::row_major> bf;
                    wmma::load_matrix_sync(bf, Wp + g * (512 * 20) + (k0 + kk) * 20, 20);
                    wmma::mma_sync(acc[g], af, bf, acc[g]);
                }
            }
        }

#pragma unroll
        for (int g = 0; g < 3; g++)
            wmma::store_matrix_sync(Sc + wrow * 52 + g * 16, acc[g], 52, wmma::mem_row_major);
        __syncwarp();

#pragma unroll
        for (int j = 0; j < 8; j++) {
            int bg = m0 + wrow + erow[j];
            int cg = c0 + ecol[j];
            const float* sc = Sc + (wrow + erow[j]) * 52 + ecol[j];
            float hgr = sc[0], hgz = sc[16], hgn = sc[32];
            float r = sigm_apx(pxr[j] + Bb[ecol[j]]      + hgr);
            float z = sigm_apx(pxz[j] + Bb[16 + ecol[j]] + hgz);
            float n = tanh_apx(pxn[j] + Bb[32 + ecol[j]] + r * (hgn + Bb[48 + ecol[j]]));
            float hn = (1.0f - z) * n + z * ph[j];
            size_t hi = (size_t)bg * HID + cg;
            g_S0[((size_t)t * BATCH + bg) * HID + cg] = hn;
            float hm = pdn[j] ? 0.0f : hn;
            g_h[hi] = hm;
            g_htf[hi] = tf32r(hm);
            if (lastt) out_hidden[hi] = hn;
        }

        if (!lastt) gsync();
    }
}

// ---------------- output head ----------------
__global__ void __launch_bounds__(256) qout_kernel(
    const float* __restrict__ w_out, const float* __restrict__ b_out,
    float* __restrict__ q)
{
    __shared__ float ws[HID * ADIM];
    for (int i = threadIdx.x; i < HID * ADIM; i += 256) ws[i] = w_out[i];
    __syncthreads();

    const size_t row = (size_t)blockIdx.x * 256 + threadIdx.x;
    const float* y = g_S0 + row * HID;
    float acc[ADIM];
#pragma unroll
    for (int a = 0; a < ADIM; a++) acc[a] = b_out[a];

    for (int c = 0; c < HID; c += 4) {
        float4 v = *(const float4*)(y + c);
        float yv[4] = {v.x, v.y, v.z, v.w};
#pragma unroll
        for (int j = 0; j < 4; j++)
#pragma unroll
            for (int a = 0; a < ADIM; a++)
                acc[a] = fmaf(yv[j], ws[(c + j) * ADIM + a], acc[a]);
    }
    float* qp = q + row * ADIM;
#pragma unroll
    for (int a = 0; a < ADIM; a++) qp[a] = acc[a];
}

// ---------------- launch ----------------
extern "C" void kernel_launch(void* const* d_in, const int* in_sizes, int n_in,
                              void* d_out, int out_size)
{
    const float* hidden    = (const float*)d_in[0];
    const float* obs       = (const float*)d_in[1];
    const int*   dones     = (const int*)d_in[2];
    const int*   last_acts = (const int*)d_in[3];
    const float* w0   = (const float*)d_in[4];
    const float* b0   = (const float*)d_in[5];
    const float* ln0s = (const float*)d_in[6];
    const float* ln0b = (const float*)d_in[7];
    const float* w1   = (const float*)d_in[8];
    const float* b1   = (const float*)d_in[9];
    const float* ln1s = (const float*)d_in[10];
    const float* ln1b = (const float*)d_in[11];
    const float* w_ir = (const float*)d_in[12];
    const float* b_ir = (const float*)d_in[13];
    const float* w_iz = (const float*)d_in[14];
    const float* b_iz = (const float*)d_in[15];
    const float* w_in = (const float*)d_in[16];
    const float* b_in = (const float*)d_in[17];
    const float* w_hr = (const float*)d_in[18];
    const float* w_hz = (const float*)d_in[19];
    const float* w_hn = (const float*)d_in[20];
    const float* b_hn = (const float*)d_in[21];
    const float* w_out = (const float*)d_in[22];
    const float* b_out = (const float*)d_in[23];

    float* out_hidden = (float*)d_out;
    float* out_q      = (float*)d_out + (size_t)BATCH * HID;

    float *S0, *S1, *Xg, *w0c, *w1c, *wgc;
    cudaGetSymbolAddress((void**)&S0,  g_S0);
    cudaGetSymbolAddress((void**)&S1,  g_S1);
    cudaGetSymbolAddress((void**)&Xg,  g_Xg);
    cudaGetSymbolAddress((void**)&w0c, g_w0c);
    cudaGetSymbolAddress((void**)&w1c, g_w1c);
    cudaGetSymbolAddress((void**)&wgc, g_wgc);

    const int gemm_smem = 3 * (GA_SZ + GB_SZ) * 4;                              // 105984 B
    const int scan_smem = (3 * 512 * 20 + 3 * SA_SZ + 128 * 52 + 64) * 4;       // 205056 B
    cudaFuncSetAttribute(gemm_db, cudaFuncAttributeMaxDynamicSharedMemorySize, gemm_smem);
    cudaFuncSetAttribute(scan_kernel, cudaFuncAttributeMaxDynamicSharedMemorySize, scan_smem);

    conv_tf32<<<(ROWS * HID / 4 + 255) / 256, 256>>>(obs, S1, ROWS * HID / 4);
    conv_tf32<<<256, 256>>>(w0, w0c, HID * HID / 4);
    conv_gates<<<1024, 256>>>(w_ir, w_iz, w_in, wgc);
    gemm_db<<<dim3(4, 512), 128, gemm_smem>>>(S1, w0c, S0, HID, HID);     // L0
    conv_tf32<<<256, 256>>>(w1, w1c, HID * HID / 4);
    mask0_kernel<<<(BATCH * HID) / 256, 256>>>(hidden, dones);
    ln_relu_kernel<<<ROWS, 128>>>(S0, S1, b0, ln0s, ln0b, w0, last_acts);
    gemm_db<<<dim3(4, 512), 128, gemm_smem>>>(S1, w1c, S0, HID, HID);     // L1
    ln_relu_kernel<<<ROWS, 128>>>(S0, S1, b1, ln1s, ln1b, nullptr, nullptr);
    gemm_db<<<dim3(12, 512), 128, gemm_smem>>>(S1, wgc, Xg, NG3, HID);    // gates

    scan_kernel<<<SC_CTAS, 256, scan_smem>>>(w_hr, w_hz, w_hn,
                                             b_ir, b_iz, b_in, b_hn,
                                             dones, out_hidden);

    qout_kernel<<<ROWS / 256, 256>>>(w_out, b_out, out_q);
}

// round 11
// speedup vs baseline: 1.1808x; 1.0463x over previous
#include <cuda_runtime.h>
#include <cuda_bf16.h>
#include <mma.h>
#include <math.h>
#include <stdint.h>

using namespace nvcuda;

#define T_STEPS 128
#define BATCH   512
#define HID     512
#define ADIM    18
#define ROWS    (T_STEPS * BATCH)   // 65536
#define NG3     (3 * HID)           // 1536
#define SC_CTAS 128

// ---------------- scratch (static __device__, no allocs) ----------------
__device__ float g_S0[(size_t)ROWS * HID];
__device__ float g_S1[(size_t)ROWS * HID];
__device__ float g_Xg[(size_t)ROWS * NG3];
__device__ float g_h  [(size_t)BATCH * HID];   // fp32 carry (exact)
__device__ float g_htf[(size_t)BATCH * HID];   // tf32-RN shadow (GEMM A operand)
__device__ float g_w0c[HID * HID];
__device__ float g_w1c[HID * HID];
__device__ float g_wgc[HID * NG3];
__device__ unsigned int g_bar;                 // monotonic grid barrier

// ---------------- cp.async helpers ----------------
__device__ __forceinline__ void cp16(uint32_t dst, const void* src) {
    asm volatile("cp.async.cg.shared.global [%0], [%1], 16;" :: "r"(dst), "l"(src));
}
#define CP_COMMIT() asm volatile("cp.async.commit_group;")
#define CP_WAIT0()  asm volatile("cp.async.wait_group 0;")
#define CP_WAIT1()  asm volatile("cp.async.wait_group 1;")

__device__ __forceinline__ float tf32r(float x) { return wmma::__float_to_tf32(x); }

__device__ __forceinline__ float tanh_apx(float x) {
    float y; asm("tanh.approx.f32 %0, %1;" : "=f"(y) : "f"(x)); return y;
}
__device__ __forceinline__ float sigm_apx(float x) { return 0.5f * tanh_apx(0.5f * x) + 0.5f; }

// ---------------- tf32-RN conversion passes ----------------
__global__ void conv_tf32(const float* __restrict__ s, float* __restrict__ d, int n4) {
    int i = blockIdx.x * 256 + threadIdx.x;
    if (i < n4) {
        float4 v = ((const float4*)s)[i];
        v.x = tf32r(v.x); v.y = tf32r(v.y); v.z = tf32r(v.z); v.w = tf32r(v.w);
        ((float4*)d)[i] = v;
    }
}

// interleave [w_ir | w_iz | w_in] column-wise into [512,1536] tf32
__global__ void conv_gates(const float* __restrict__ wir, const float* __restrict__ wiz,
                           const float* __restrict__ win, float* __restrict__ dst) {
    int i = blockIdx.x * 256 + threadIdx.x;   // 262144
    int k = i >> 9, c = i & 511;
    size_t o = (size_t)k * NG3 + c;
    dst[o]        = tf32r(wir[i]);
    dst[o + 512]  = tf32r(wiz[i]);
    dst[o + 1024] = tf32r(win[i]);
}

// ---------------- 3-stage TF32 GEMM: BM=128 BN=128 BK=32, 4 warps, 64x64 warp tile ----
#define GA_LD 36
#define GB_LD 132
#define GA_SZ (128 * GA_LD)
#define GB_SZ (32 * GB_LD)

__global__ void __launch_bounds__(128, 2) gemm_db(
    const float* __restrict__ A, const float* __restrict__ B,
    float* __restrict__ C, int N, int K)
{
    extern __shared__ float sm[];
    float* As = sm;
    float* Bs = sm + 3 * GA_SZ;

    const int tid = threadIdx.x;
    const int wid = tid >> 5;
    const size_t m0 = (size_t)blockIdx.y * 128;
    const int n0 = blockIdx.x * 128;
    const int wm = (wid >> 1) * 64;    // 2x2 warp grid, 64x64 per warp
    const int wn = (wid & 1) * 64;

    wmma::fragment<wmma::accumulator, 16, 16, 8, float> acc[4][4];
#pragma unroll
    for (int i = 0; i < 4; i++)
#pragma unroll
        for (int j = 0; j < 4; j++) wmma::fill_fragment(acc[i][j], 0.0f);

    const int NK = K / 32;

    auto load_stage = [&](int kc, int buf) {
        int k0 = kc * 32;
#pragma unroll
        for (int l = 0; l < 8; l++) {
            int f = tid + l * 128;
            int r = f >> 3, c = (f & 7) * 4;
            cp16((uint32_t)__cvta_generic_to_shared(As + buf * GA_SZ + r * GA_LD + c),
                 A + (m0 + r) * (size_t)K + k0 + c);
        }
#pragma unroll
        for (int l = 0; l < 8; l++) {
            int f = tid + l * 128;
            int r = f >> 5, c = (f & 31) * 4;
            cp16((uint32_t)__cvta_generic_to_shared(Bs + buf * GB_SZ + r * GB_LD + c),
                 B + (size_t)(k0 + r) * N + n0 + c);
        }
    };

    load_stage(0, 0); CP_COMMIT();
    load_stage(1, 1); CP_COMMIT();

    for (int kc = 0; kc < NK; kc++) {
        int buf = kc % 3;
        if (kc + 1 < NK) CP_WAIT1(); else CP_WAIT0();
        __syncthreads();
        if (kc + 2 < NK) { load_stage(kc + 2, (kc + 2) % 3); CP_COMMIT(); }
#pragma unroll
        for (int kk = 0; kk < 32; kk += 8) {
            wmma::fragment<wmma::matrix_a, 16, 16, 8, wmma::precision::tf32, wmma::row_major> af[4];
            wmma::fragment<wmma::matrix_b, 16, 16, 8, wmma::precision::tf32, wmma::row_major> bf[4];
#pragma unroll
            for (int i = 0; i < 4; i++)
                wmma::load_matrix_sync(af[i], As + buf * GA_SZ + (wm + 16 * i) * GA_LD + kk, GA_LD);
#pragma unroll
            for (int j = 0; j < 4; j++)
                wmma::load_matrix_sync(bf[j], Bs + buf * GB_SZ + kk * GB_LD + wn + 16 * j, GB_LD);
#pragma unroll
            for (int i = 0; i < 4; i++)
#pragma unroll
                for (int j = 0; j < 4; j++) wmma::mma_sync(acc[i][j], af[i], bf[j], acc[i][j]);
        }
    }
    __syncthreads();
#pragma unroll
    for (int i = 0; i < 4; i++)
#pragma unroll
        for (int j = 0; j < 4; j++)
            wmma::store_matrix_sync(C + (m0 + wm + 16 * i) * (size_t)N + n0 + wn + 16 * j,
                                    acc[i][j], N, wmma::mem_row_major);
}

// ---------------- LayerNorm(+bias,+one-hot) + ReLU, tf32-RN output ----------------
__global__ void __launch_bounds__(128) ln_relu_kernel(
    const float* __restrict__ in, float* __restrict__ out,
    const float* __restrict__ addb,
    const float* __restrict__ lns, const float* __restrict__ lnb,
    const float* __restrict__ w_oh, const int* __restrict__ acts)
{
    const int row = blockIdx.x;
    const int tid = threadIdx.x;
    const float* ip = in + (size_t)row * HID;

    float4 v = *(const float4*)(ip + tid * 4);
    float4 a = *(const float4*)(addb + tid * 4);
    v.x += a.x; v.y += a.y; v.z += a.z; v.w += a.w;
    if (w_oh) {
        const float* oh = w_oh + (size_t)(512 + acts[row]) * HID;
        float4 o = *(const float4*)(oh + tid * 4);
        v.x += o.x; v.y += o.y; v.z += o.z; v.w += o.w;
    }
    float sum = v.x + v.y + v.z + v.w;
    float sq  = v.x * v.x + v.y * v.y + v.z * v.z + v.w * v.w;

    __shared__ float red[8];
#pragma unroll
    for (int off = 16; off > 0; off >>= 1) {
        sum += __shfl_down_sync(0xFFFFFFFFu, sum, off);
        sq  += __shfl_down_sync(0xFFFFFFFFu, sq,  off);
    }
    if ((tid & 31) == 0) { red[tid >> 5] = sum; red[4 + (tid >> 5)] = sq; }
    __syncthreads();
    float ts = red[0] + red[1] + red[2] + red[3];
    float tq = red[4] + red[5] + red[6] + red[7];
    float mean = ts * (1.0f / HID);
    float var  = tq * (1.0f / HID) - mean * mean;
    float inv  = rsqrtf(var + 1e-6f);

    float4 sc = *(const float4*)(lns + tid * 4);
    float4 bb = *(const float4*)(lnb + tid * 4);
    float4 r;
    r.x = tf32r(fmaxf((v.x - mean) * inv * sc.x + bb.x, 0.0f));
    r.y = tf32r(fmaxf((v.y - mean) * inv * sc.y + bb.y, 0.0f));
    r.z = tf32r(fmaxf((v.z - mean) * inv * sc.z + bb.z, 0.0f));
    r.w = tf32r(fmaxf((v.w - mean) * inv * sc.w + bb.w, 0.0f));
    *(float4*)(out + (size_t)row * HID + tid * 4) = r;
}

// ---------------- initial done-mask ----------------
__global__ void mask0_kernel(const float* __restrict__ hidden_in,
                             const int* __restrict__ dones)
{
    int i = blockIdx.x * blockDim.x + threadIdx.x;
    int b = i >> 9;
    float v = dones[b] ? 0.0f : hidden_in[i];
    g_h[i] = v;
    g_htf[i] = tf32r(v);
}

// ---------------- persistent fused GRU scan v4: warp-private A strips, no CTA syncs ----
__device__ __forceinline__ void gsync() {
    __threadfence();
    __syncthreads();
    if (threadIdx.x == 0) {
        unsigned int old = atomicAdd(&g_bar, 1u);
        unsigned int target = (old / SC_CTAS + 1u) * SC_CTAS;
        while (*((volatile unsigned int*)&g_bar) < target) { }
        __threadfence();
    }
    __syncthreads();
}

#define ST_LD 36
#define ST_BUF (16 * ST_LD)        // 576 floats per buffer
#define ST_WARP (3 * ST_BUF)       // 1728 floats per warp

__global__ void __launch_bounds__(256, 1) scan_kernel(
    const float* __restrict__ w_hr, const float* __restrict__ w_hz, const float* __restrict__ w_hn,
    const float* __restrict__ b_ir, const float* __restrict__ b_iz,
    const float* __restrict__ b_in, const float* __restrict__ b_hn,
    const int* __restrict__ dones,
    float* __restrict__ out_hidden)
{
    extern __shared__ float ssm[];
    float* Wp = ssm;                      // 3 * 512 * 20  = 30720
    float* At = Wp + 3 * 512 * 20;        // 8 * ST_WARP   = 13824
    float* Sc = At + 8 * ST_WARP;         // 128 * 52      = 6656
    float* Bb = Sc + 128 * 52;            // 64

    const int tid  = threadIdx.x;
    const int wid  = tid >> 5;
    const int lane = tid & 31;
    const int bx   = blockIdx.x;
    const int c0   = (bx & 31) * 16;
    const int m0   = (bx >> 5) * 128;

    // prologue: weight panels [512 x 16] x3 as tf32-RN + bias slices
    {
        const float* Ws[3] = {w_hr, w_hz, w_hn};
#pragma unroll
        for (int g = 0; g < 3; g++) {
            for (int i4 = tid; i4 < 2048; i4 += 256) {
                int k = i4 >> 2, cc = (i4 & 3) * 4;
                float4 v = *(const float4*)(Ws[g] + (size_t)k * HID + c0 + cc);
                float* d = Wp + g * (512 * 20) + k * 20 + cc;
                d[0] = tf32r(v.x); d[1] = tf32r(v.y); d[2] = tf32r(v.z); d[3] = tf32r(v.w);
            }
        }
        if (tid < 16) {
            Bb[tid]      = b_ir[c0 + tid];
            Bb[16 + tid] = b_iz[c0 + tid];
            Bb[32 + tid] = b_in[c0 + tid];
            Bb[48 + tid] = b_hn[c0 + tid];
        }
    }
    __syncthreads();

    const int wrow = wid * 16;
    float* Wstrip = At + wid * ST_WARP;

    // per-warp A-strip load: 16 rows x 32 cols = 128 float4, 4 per lane
    auto load_strip = [&](int k0, int buf) {
        float* dst = Wstrip + buf * ST_BUF;
#pragma unroll
        for (int i = 0; i < 4; i++) {
            int f = lane + i * 32;
            int r = f >> 3, c = (f & 7) * 4;
            cp16((uint32_t)__cvta_generic_to_shared(dst + r * ST_LD + c),
                 g_htf + (size_t)(m0 + wrow + r) * HID + k0 + c);
        }
    };

    int erow[8], ecol[8];
#pragma unroll
    for (int j = 0; j < 8; j++) { int e = j * 32 + lane; erow[j] = e >> 4; ecol[j] = e & 15; }

    for (int t = 0; t < T_STEPS; t++) {
        const bool lastt = (t == T_STEPS - 1);

        // prefetch step inputs (latency hidden under GEMM)
        float pxr[8], pxz[8], pxn[8], ph[8];
        int pdn[8];
#pragma unroll
        for (int j = 0; j < 8; j++) {
            int bg = m0 + wrow + erow[j];
            int cg = c0 + ecol[j];
            const float* xg = g_Xg + ((size_t)t * BATCH + bg) * NG3 + cg;
            pxr[j] = __ldcg(xg);
            pxz[j] = __ldcg(xg + 512);
            pxn[j] = __ldcg(xg + 1024);
            ph[j]  = g_h[(size_t)bg * HID + cg];
            pdn[j] = lastt ? 0 : dones[(t + 1) * BATCH + bg];
        }

        // ---- GEMM: warp-private pipeline, zero CTA barriers ----
        wmma::fragment<wmma::accumulator, 16, 16, 8, float> acc[3];
#pragma unroll
        for (int g = 0; g < 3; g++) wmma::fill_fragment(acc[g], 0.0f);

        load_strip(0, 0); CP_COMMIT();
        load_strip(32, 1); CP_COMMIT();

        for (int kc = 0; kc < 16; kc++) {
            int buf = kc % 3;
            if (kc + 1 < 16) CP_WAIT1(); else CP_WAIT0();
            __syncwarp();
            if (kc + 2 < 16) { load_strip((kc + 2) * 32, (kc + 2) % 3); CP_COMMIT(); }
            int k0 = kc * 32;
            const float* sa = Wstrip + buf * ST_BUF;
#pragma unroll
            for (int kk = 0; kk < 32; kk += 8) {
                wmma::fragment<wmma::matrix_a, 16, 16, 8, wmma::precision::tf32, wmma::row_major> af;
                wmma::load_matrix_sync(af, sa + kk, ST_LD);
#pragma unroll
                for (int g = 0; g < 3; g++) {
                    wmma::fragment<wmma::matrix_b, 16, 16, 8, wmma::precision::tf32, wmma::row_major> bf;
                    wmma::load_matrix_sync(bf, Wp + g * (512 * 20) + (k0 + kk) * 20, 20);
                    wmma::mma_sync(acc[g], af, bf, acc[g]);
                }
            }
        }

        // spill accs to this warp's private Sc slab
#pragma unroll
        for (int g = 0; g < 3; g++)
            wmma::store_matrix_sync(Sc + wrow * 52 + g * 16, acc[g], 52, wmma::mem_row_major);
        __syncwarp();

        // ---- gates (warp-local; overlaps other warps' GEMM) ----
#pragma unroll
        for (int j = 0; j < 8; j++) {
            int bg = m0 + wrow + erow[j];
            int cg = c0 + ecol[j];
            const float* sc = Sc + (wrow + erow[j]) * 52 + ecol[j];
            float hgr = sc[0], hgz = sc[16], hgn = sc[32];
            float r = sigm_apx(pxr[j] + Bb[ecol[j]]      + hgr);
            float z = sigm_apx(pxz[j] + Bb[16 + ecol[j]] + hgz);
            float n = tanh_apx(pxn[j] + Bb[32 + ecol[j]] + r * (hgn + Bb[48 + ecol[j]]));
            float hn = (1.0f - z) * n + z * ph[j];
            size_t hi = (size_t)bg * HID + cg;
            g_S0[((size_t)t * BATCH + bg) * HID + cg] = hn;
            float hm = pdn[j] ? 0.0f : hn;
            g_h[hi] = hm;
            g_htf[hi] = tf32r(hm);
            if (lastt) out_hidden[hi] = hn;
        }

        if (!lastt) gsync();
    }
}

// ---------------- output head ----------------
__global__ void __launch_bounds__(256) qout_kernel(
    const float* __restrict__ w_out, const float* __restrict__ b_out,
    float* __restrict__ q)
{
    __shared__ float ws[HID * ADIM];
    for (int i = threadIdx.x; i < HID * ADIM; i += 256) ws[i] = w_out[i];
    __syncthreads();

    const size_t row = (size_t)blockIdx.x * 256 + threadIdx.x;
    const float* y = g_S0 + row * HID;
    float acc[ADIM];
#pragma unroll
    for (int a = 0; a < ADIM; a++) acc[a] = b_out[a];

    for (int c = 0; c < HID; c += 4) {
        float4 v = *(const float4*)(y + c);
        float yv[4] = {v.x, v.y, v.z, v.w};
#pragma unroll
        for (int j = 0; j < 4; j++)
#pragma unroll
            for (int a = 0; a < ADIM; a++)
                acc[a] = fmaf(yv[j], ws[(c + j) * ADIM + a], acc[a]);
    }
    float* qp = q + row * ADIM;
#pragma unroll
    for (int a = 0; a < ADIM; a++) qp[a] = acc[a];
}

// ---------------- launch ----------------
extern "C" void kernel_launch(void* const* d_in, const int* in_sizes, int n_in,
                              void* d_out, int out_size)
{
    const float* hidden    = (const float*)d_in[0];
    const float* obs       = (const float*)d_in[1];
    const int*   dones     = (const int*)d_in[2];
    const int*   last_acts = (const int*)d_in[3];
    const float* w0   = (const float*)d_in[4];
    const float* b0   = (const float*)d_in[5];
    const float* ln0s = (const float*)d_in[6];
    const float* ln0b = (const float*)d_in[7];
    const float* w1   = (const float*)d_in[8];
    const float* b1   = (const float*)d_in[9];
    const float* ln1s = (const float*)d_in[10];
    const float* ln1b = (const float*)d_in[11];
    const float* w_ir = (const float*)d_in[12];
    const float* b_ir = (const float*)d_in[13];
    const float* w_iz = (const float*)d_in[14];
    const float* b_iz = (const float*)d_in[15];
    const float* w_in = (const float*)d_in[16];
    const float* b_in = (const float*)d_in[17];
    const float* w_hr = (const float*)d_in[18];
    const float* w_hz = (const float*)d_in[19];
    const float* w_hn = (const float*)d_in[20];
    const float* b_hn = (const float*)d_in[21];
    const float* w_out = (const float*)d_in[22];
    const float* b_out = (const float*)d_in[23];

    float* out_hidden = (float*)d_out;
    float* out_q      = (float*)d_out + (size_t)BATCH * HID;

    float *S0, *S1, *Xg, *w0c, *w1c, *wgc;
    cudaGetSymbolAddress((void**)&S0,  g_S0);
    cudaGetSymbolAddress((void**)&S1,  g_S1);
    cudaGetSymbolAddress((void**)&Xg,  g_Xg);
    cudaGetSymbolAddress((void**)&w0c, g_w0c);
    cudaGetSymbolAddress((void**)&w1c, g_w1c);
    cudaGetSymbolAddress((void**)&wgc, g_wgc);

    const int gemm_smem = 3 * (GA_SZ + GB_SZ) * 4;                              // 105984 B
    const int scan_smem = (3 * 512 * 20 + 8 * ST_WARP + 128 * 52 + 64) * 4;     // 205056 B
    cudaFuncSetAttribute(gemm_db, cudaFuncAttributeMaxDynamicSharedMemorySize, gemm_smem);
    cudaFuncSetAttribute(scan_kernel, cudaFuncAttributeMaxDynamicSharedMemorySize, scan_smem);

    conv_tf32<<<(ROWS * HID / 4 + 255) / 256, 256>>>(obs, S1, ROWS * HID / 4);
    conv_tf32<<<256, 256>>>(w0, w0c, HID * HID / 4);
    conv_gates<<<1024, 256>>>(w_ir, w_iz, w_in, wgc);
    gemm_db<<<dim3(4, 512), 128, gemm_smem>>>(S1, w0c, S0, HID, HID);     // L0
    conv_tf32<<<256, 256>>>(w1, w1c, HID * HID / 4);
    mask0_kernel<<<(BATCH * HID) / 256, 256>>>(hidden, dones);
    ln_relu_kernel<<<ROWS, 128>>>(S0, S1, b0, ln0s, ln0b, w0, last_acts);
    gemm_db<<<dim3(4, 512), 128, gemm_smem>>>(S1, w1c, S0, HID, HID);     // L1
    ln_relu_kernel<<<ROWS, 128>>>(S0, S1, b1, ln1s, ln1b, nullptr, nullptr);
    gemm_db<<<dim3(12, 512), 128, gemm_smem>>>(S1, wgc, Xg, NG3, HID);    // gates

    scan_kernel<<<SC_CTAS, 256, scan_smem>>>(w_hr, w_hz, w_hn,
                                             b_ir, b_iz, b_in, b_hn,
                                             dones, out_hidden);

    qout_kernel<<<ROWS / 256, 256>>>(w_out, b_out, out_q);
}

// round 12
// speedup vs baseline: 1.2120x; 1.0264x over previous
#include <cuda_runtime.h>
#include <cuda_bf16.h>
#include <mma.h>
#include <math.h>
#include <stdint.h>

using namespace nvcuda;

#define T_STEPS 128
#define BATCH   512
#define HID     512
#define ADIM    18
#define ROWS    (T_STEPS * BATCH)   // 65536
#define NG3     (3 * HID)           // 1536
#define SC_CTAS 128
#define SC_GRP  32

// ---------------- scratch (static __device__, no allocs) ----------------
__device__ float g_S0[(size_t)ROWS * HID];
__device__ float g_S1[(size_t)ROWS * HID];
__device__ float g_Xg[(size_t)ROWS * NG3];
__device__ float g_htf[(size_t)BATCH * HID];   // tf32-RN carry (sole h state)
__device__ float g_w0c[HID * HID];
__device__ float g_w1c[HID * HID];
__device__ float g_wgc[HID * NG3];
__device__ unsigned int g_barg[4 * 32];        // 4 group barriers, 128B apart

// ---------------- cp.async helpers ----------------
__device__ __forceinline__ void cp16(uint32_t dst, const void* src) {
    asm volatile("cp.async.cg.shared.global [%0], [%1], 16;" :: "r"(dst), "l"(src));
}
#define CP_COMMIT() asm volatile("cp.async.commit_group;")
#define CP_WAIT0()  asm volatile("cp.async.wait_group 0;")
#define CP_WAIT1()  asm volatile("cp.async.wait_group 1;")

__device__ __forceinline__ float tf32r(float x) { return wmma::__float_to_tf32(x); }

__device__ __forceinline__ float tanh_apx(float x) {
    float y; asm("tanh.approx.f32 %0, %1;" : "=f"(y) : "f"(x)); return y;
}
__device__ __forceinline__ float sigm_apx(float x) { return 0.5f * tanh_apx(0.5f * x) + 0.5f; }

// ---------------- tf32-RN conversion passes ----------------
__global__ void conv_tf32(const float* __restrict__ s, float* __restrict__ d, int n4) {
    int i = blockIdx.x * 256 + threadIdx.x;
    if (i < n4) {
        float4 v = ((const float4*)s)[i];
        v.x = tf32r(v.x); v.y = tf32r(v.y); v.z = tf32r(v.z); v.w = tf32r(v.w);
        ((float4*)d)[i] = v;
    }
}

// interleave [w_ir | w_iz | w_in] column-wise into [512,1536] tf32
__global__ void conv_gates(const float* __restrict__ wir, const float* __restrict__ wiz,
                           const float* __restrict__ win, float* __restrict__ dst) {
    int i = blockIdx.x * 256 + threadIdx.x;   // 262144
    int k = i >> 9, c = i & 511;
    size_t o = (size_t)k * NG3 + c;
    dst[o]        = tf32r(wir[i]);
    dst[o + 512]  = tf32r(wiz[i]);
    dst[o + 1024] = tf32r(win[i]);
}

// ---------------- 3-stage TF32 GEMM: BM=128 BN=128 BK=32, 4 warps, 64x64 warp tile ----
#define GA_LD 36
#define GB_LD 132
#define GA_SZ (128 * GA_LD)
#define GB_SZ (32 * GB_LD)

__global__ void __launch_bounds__(128, 2) gemm_db(
    const float* __restrict__ A, const float* __restrict__ B,
    float* __restrict__ C, int N, int K)
{
    extern __shared__ float sm[];
    float* As = sm;
    float* Bs = sm + 3 * GA_SZ;

    const int tid = threadIdx.x;
    const int wid = tid >> 5;
    const size_t m0 = (size_t)blockIdx.y * 128;
    const int n0 = blockIdx.x * 128;
    const int wm = (wid >> 1) * 64;
    const int wn = (wid & 1) * 64;

    wmma::fragment<wmma::accumulator, 16, 16, 8, float> acc[4][4];
#pragma unroll
    for (int i = 0; i < 4; i++)
#pragma unroll
        for (int j = 0; j < 4; j++) wmma::fill_fragment(acc[i][j], 0.0f);

    const int NK = K / 32;

    auto load_stage = [&](int kc, int buf) {
        int k0 = kc * 32;
#pragma unroll
        for (int l = 0; l < 8; l++) {
            int f = tid + l * 128;
            int r = f >> 3, c = (f & 7) * 4;
            cp16((uint32_t)__cvta_generic_to_shared(As + buf * GA_SZ + r * GA_LD + c),
                 A + (m0 + r) * (size_t)K + k0 + c);
        }
#pragma unroll
        for (int l = 0; l < 8; l++) {
            int f = tid + l * 128;
            int r = f >> 5, c = (f & 31) * 4;
            cp16((uint32_t)__cvta_generic_to_shared(Bs + buf * GB_SZ + r * GB_LD + c),
                 B + (size_t)(k0 + r) * N + n0 + c);
        }
    };

    load_stage(0, 0); CP_COMMIT();
    load_stage(1, 1); CP_COMMIT();

    for (int kc = 0; kc < NK; kc++) {
        int buf = kc % 3;
        if (kc + 1 < NK) CP_WAIT1(); else CP_WAIT0();
        __syncthreads();
        if (kc + 2 < NK) { load_stage(kc + 2, (kc + 2) % 3); CP_COMMIT(); }
#pragma unroll
        for (int kk = 0; kk < 32; kk += 8) {
            wmma::fragment<wmma::matrix_a, 16, 16, 8, wmma::precision::tf32, wmma::row_major> af[4];
            wmma::fragment<wmma::matrix_b, 16, 16, 8, wmma::precision::tf32, wmma::row_major> bf[4];
#pragma unroll
            for (int i = 0; i < 4; i++)
                wmma::load_matrix_sync(af[i], As + buf * GA_SZ + (wm + 16 * i) * GA_LD + kk, GA_LD);
#pragma unroll
            for (int j = 0; j < 4; j++)
                wmma::load_matrix_sync(bf[j], Bs + buf * GB_SZ + kk * GB_LD + wn + 16 * j, GB_LD);
#pragma unroll
            for (int i = 0; i < 4; i++)
#pragma unroll
                for (int j = 0; j < 4; j++) wmma::mma_sync(acc[i][j], af[i], bf[j], acc[i][j]);
        }
    }
    __syncthreads();
#pragma unroll
    for (int i = 0; i < 4; i++)
#pragma unroll
        for (int j = 0; j < 4; j++)
            wmma::store_matrix_sync(C + (m0 + wm + 16 * i) * (size_t)N + n0 + wn + 16 * j,
                                    acc[i][j], N, wmma::mem_row_major);
}

// ---------------- LayerNorm(+bias,+one-hot) + ReLU, tf32-RN output ----------------
__global__ void __launch_bounds__(128) ln_relu_kernel(
    const float* __restrict__ in, float* __restrict__ out,
    const float* __restrict__ addb,
    const float* __restrict__ lns, const float* __restrict__ lnb,
    const float* __restrict__ w_oh, const int* __restrict__ acts)
{
    const int row = blockIdx.x;
    const int tid = threadIdx.x;
    const float* ip = in + (size_t)row * HID;

    float4 v = *(const float4*)(ip + tid * 4);
    float4 a = *(const float4*)(addb + tid * 4);
    v.x += a.x; v.y += a.y; v.z += a.z; v.w += a.w;
    if (w_oh) {
        const float* oh = w_oh + (size_t)(512 + acts[row]) * HID;
        float4 o = *(const float4*)(oh + tid * 4);
        v.x += o.x; v.y += o.y; v.z += o.z; v.w += o.w;
    }
    float sum = v.x + v.y + v.z + v.w;
    float sq  = v.x * v.x + v.y * v.y + v.z * v.z + v.w * v.w;

    __shared__ float red[8];
#pragma unroll
    for (int off = 16; off > 0; off >>= 1) {
        sum += __shfl_down_sync(0xFFFFFFFFu, sum, off);
        sq  += __shfl_down_sync(0xFFFFFFFFu, sq,  off);
    }
    if ((tid & 31) == 0) { red[tid >> 5] = sum; red[4 + (tid >> 5)] = sq; }
    __syncthreads();
    float ts = red[0] + red[1] + red[2] + red[3];
    float tq = red[4] + red[5] + red[6] + red[7];
    float mean = ts * (1.0f / HID);
    float var  = tq * (1.0f / HID) - mean * mean;
    float inv  = rsqrtf(var + 1e-6f);

    float4 sc = *(const float4*)(lns + tid * 4);
    float4 bb = *(const float4*)(lnb + tid * 4);
    float4 r;
    r.x = tf32r(fmaxf((v.x - mean) * inv * sc.x + bb.x, 0.0f));
    r.y = tf32r(fmaxf((v.y - mean) * inv * sc.y + bb.y, 0.0f));
    r.z = tf32r(fmaxf((v.z - mean) * inv * sc.z + bb.z, 0.0f));
    r.w = tf32r(fmaxf((v.w - mean) * inv * sc.w + bb.w, 0.0f));
    *(float4*)(out + (size_t)row * HID + tid * 4) = r;
}

// ---------------- initial done-mask (tf32 carry) ----------------
__global__ void mask0_kernel(const float* __restrict__ hidden_in,
                             const int* __restrict__ dones)
{
    int i = blockIdx.x * blockDim.x + threadIdx.x;
    int b = i >> 9;
    float v = dones[b] ? 0.0f : hidden_in[i];
    g_htf[i] = tf32r(v);
}

// ---------------- persistent fused GRU scan v5 ----------------
// 128 CTAs x 256 thr; 4 barrier groups of 32 CTAs (per m-panel).
__device__ __forceinline__ void gsync_grp(int grp) {
    __threadfence();
    __syncthreads();
    if (threadIdx.x == 0) {
        unsigned int* ctr = &g_barg[grp * 32];
        unsigned int old = atomicAdd(ctr, 1u);
        unsigned int target = (old / SC_GRP + 1u) * SC_GRP;
        while (*((volatile unsigned int*)ctr) < target) { }
        __threadfence();
    }
    __syncthreads();
}

#define ST_LD 36
#define ST_BUF (16 * ST_LD)
#define ST_WARP (3 * ST_BUF)

__global__ void __launch_bounds__(256, 1) scan_kernel(
    const float* __restrict__ w_hr, const float* __restrict__ w_hz, const float* __restrict__ w_hn,
    const float* __restrict__ b_ir, const float* __restrict__ b_iz,
    const float* __restrict__ b_in, const float* __restrict__ b_hn,
    const int* __restrict__ dones,
    float* __restrict__ out_hidden)
{
    extern __shared__ float ssm[];
    float* Wp = ssm;                      // 3 * 512 * 20
    float* At = Wp + 3 * 512 * 20;        // 8 * ST_WARP
    float* Sc = At + 8 * ST_WARP;         // 128 * 52
    float* Bb = Sc + 128 * 52;            // 64

    const int tid  = threadIdx.x;
    const int wid  = tid >> 5;
    const int lane = tid & 31;
    const int bx   = blockIdx.x;
    const int c0   = (bx & 31) * 16;
    const int grp  = bx >> 5;
    const int m0   = grp * 128;

    {
        const float* Ws[3] = {w_hr, w_hz, w_hn};
#pragma unroll
        for (int g = 0; g < 3; g++) {
            for (int i4 = tid; i4 < 2048; i4 += 256) {
                int k = i4 >> 2, cc = (i4 & 3) * 4;
                float4 v = *(const float4*)(Ws[g] + (size_t)k * HID + c0 + cc);
                float* d = Wp + g * (512 * 20) + k * 20 + cc;
                d[0] = tf32r(v.x); d[1] = tf32r(v.y); d[2] = tf32r(v.z); d[3] = tf32r(v.w);
            }
        }
        if (tid < 16) {
            Bb[tid]      = b_ir[c0 + tid];
            Bb[16 + tid] = b_iz[c0 + tid];
            Bb[32 + tid] = b_in[c0 + tid];
            Bb[48 + tid] = b_hn[c0 + tid];
        }
    }
    __syncthreads();

    const int wrow = wid * 16;
    float* Wstrip = At + wid * ST_WARP;

    auto load_strip = [&](int k0, int buf) {
        float* dst = Wstrip + buf * ST_BUF;
#pragma unroll
        for (int i = 0; i < 4; i++) {
            int f = lane + i * 32;
            int r = f >> 3, c = (f & 7) * 4;
            cp16((uint32_t)__cvta_generic_to_shared(dst + r * ST_LD + c),
                 g_htf + (size_t)(m0 + wrow + r) * HID + k0 + c);
        }
    };

    int erow[8], ecol[8];
#pragma unroll
    for (int j = 0; j < 8; j++) { int e = j * 32 + lane; erow[j] = e >> 4; ecol[j] = e & 15; }

    for (int t = 0; t < T_STEPS; t++) {
        const bool lastt = (t == T_STEPS - 1);

        // ---- prefetch block A: elements 0-3 + dones (reduced burst) ----
        float pxr[8], pxz[8], pxn[8], ph[8];
        int pdn[8];
#pragma unroll
        for (int j = 0; j < 4; j++) {
            int bg = m0 + wrow + erow[j];
            int cg = c0 + ecol[j];
            const float* xg = g_Xg + ((size_t)t * BATCH + bg) * NG3 + cg;
            pxr[j] = __ldcg(xg);
            pxz[j] = __ldcg(xg + 512);
            pxn[j] = __ldcg(xg + 1024);
            ph[j]  = g_htf[(size_t)bg * HID + cg];
            pdn[j] = lastt ? 0 : dones[(t + 1) * BATCH + bg];
        }

        wmma::fragment<wmma::accumulator, 16, 16, 8, float> acc[3];
#pragma unroll
        for (int g = 0; g < 3; g++) wmma::fill_fragment(acc[g], 0.0f);

        load_strip(0, 0); CP_COMMIT();
        load_strip(32, 1); CP_COMMIT();

        // ---- kc half 1: 0..7 ----
        for (int kc = 0; kc < 8; kc++) {
            int buf = kc % 3;
            CP_WAIT1();
            __syncwarp();
            load_strip((kc + 2) * 32, (kc + 2) % 3); CP_COMMIT();
            int k0 = kc * 32;
            const float* sa = Wstrip + buf * ST_BUF;
#pragma unroll
            for (int kk = 0; kk < 32; kk += 8) {
                wmma::fragment<wmma::matrix_a, 16, 16, 8, wmma::precision::tf32, wmma::row_major> af;
                wmma::load_matrix_sync(af, sa + kk, ST_LD);
#pragma unroll
                for (int g = 0; g < 3; g++) {
                    wmma::fragment<wmma::matrix_b, 16, 16, 8, wmma::precision::tf32, wmma::row_major> bf;
                    wmma::load_matrix_sync(bf, Wp + g * (512 * 20) + (k0 + kk) * 20, 20);
                    wmma::mma_sync(acc[g], af, bf, acc[g]);
                }
            }
        }

        // ---- prefetch block B: elements 4-7 ----
#pragma unroll
        for (int j = 4; j < 8; j++) {
            int bg = m0 + wrow + erow[j];
            int cg = c0 + ecol[j];
            const float* xg = g_Xg + ((size_t)t * BATCH + bg) * NG3 + cg;
            pxr[j] = __ldcg(xg);
            pxz[j] = __ldcg(xg + 512);
            pxn[j] = __ldcg(xg + 1024);
            ph[j]  = g_htf[(size_t)bg * HID + cg];
            pdn[j] = lastt ? 0 : dones[(t + 1) * BATCH + bg];
        }

        // ---- kc half 2: 8..15 ----
        for (int kc = 8; kc < 16; kc++) {
            int buf = kc % 3;
            if (kc + 1 < 16) CP_WAIT1(); else CP_WAIT0();
            __syncwarp();
            if (kc + 2 < 16) { load_strip((kc + 2) * 32, (kc + 2) % 3); CP_COMMIT(); }
            int k0 = kc * 32;
            const float* sa = Wstrip + buf * ST_BUF;
#pragma unroll
            for (int kk = 0; kk < 32; kk += 8) {
                wmma::fragment<wmma::matrix_a, 16, 16, 8, wmma::precision::tf32, wmma::row_major> af;
                wmma::load_matrix_sync(af, sa + kk, ST_LD);
#pragma unroll
                for (int g = 0; g < 3; g++) {
                    wmma::fragment<wmma::matrix_b, 16, 16, 8, wmma::precision::tf32, wmma::row_major> bf;
                    wmma::load_matrix_sync(bf, Wp + g * (512 * 20) + (k0 + kk) * 20, 20);
                    wmma::mma_sync(acc[g], af, bf, acc[g]);
                }
            }
        }

        // spill accs to this warp's private Sc slab
#pragma unroll
        for (int g = 0; g < 3; g++)
            wmma::store_matrix_sync(Sc + wrow * 52 + g * 16, acc[g], 52, wmma::mem_row_major);
        __syncwarp();

        // ---- gates (warp-local) ----
#pragma unroll
        for (int j = 0; j < 8; j++) {
            int bg = m0 + wrow + erow[j];
            int cg = c0 + ecol[j];
            const float* sc = Sc + (wrow + erow[j]) * 52 + ecol[j];
            float hgr = sc[0], hgz = sc[16], hgn = sc[32];
            float r = sigm_apx(pxr[j] + Bb[ecol[j]]      + hgr);
            float z = sigm_apx(pxz[j] + Bb[16 + ecol[j]] + hgz);
            float n = tanh_apx(pxn[j] + Bb[32 + ecol[j]] + r * (hgn + Bb[48 + ecol[j]]));
            float hn = (1.0f - z) * n + z * ph[j];
            size_t hi = (size_t)bg * HID + cg;
            g_S0[((size_t)t * BATCH + bg) * HID + cg] = hn;
            float hm = pdn[j] ? 0.0f : hn;
            g_htf[hi] = tf32r(hm);
            if (lastt) out_hidden[hi] = hn;
        }

        if (!lastt) gsync_grp(grp);
    }
}

// ---------------- output head ----------------
__global__ void __launch_bounds__(256) qout_kernel(
    const float* __restrict__ w_out, const float* __restrict__ b_out,
    float* __restrict__ q)
{
    __shared__ float ws[HID * ADIM];
    for (int i = threadIdx.x; i < HID * ADIM; i += 256) ws[i] = w_out[i];
    __syncthreads();

    const size_t row = (size_t)blockIdx.x * 256 + threadIdx.x;
    const float* y = g_S0 + row * HID;
    float acc[ADIM];
#pragma unroll
    for (int a = 0; a < ADIM; a++) acc[a] = b_out[a];

    for (int c = 0; c < HID; c += 4) {
        float4 v = *(const float4*)(y + c);
        float yv[4] = {v.x, v.y, v.z, v.w};
#pragma unroll
        for (int j = 0; j < 4; j++)
#pragma unroll
            for (int a = 0; a < ADIM; a++)
                acc[a] = fmaf(yv[j], ws[(c + j) * ADIM + a], acc[a]);
    }
    float* qp = q + row * ADIM;
#pragma unroll
    for (int a = 0; a < ADIM; a++) qp[a] = acc[a];
}

// ---------------- launch ----------------
extern "C" void kernel_launch(void* const* d_in, const int* in_sizes, int n_in,
                              void* d_out, int out_size)
{
    const float* hidden    = (const float*)d_in[0];
    const float* obs       = (const float*)d_in[1];
    const int*   dones     = (const int*)d_in[2];
    const int*   last_acts = (const int*)d_in[3];
    const float* w0   = (const float*)d_in[4];
    const float* b0   = (const float*)d_in[5];
    const float* ln0s = (const float*)d_in[6];
    const float* ln0b = (const float*)d_in[7];
    const float* w1   = (const float*)d_in[8];
    const float* b1   = (const float*)d_in[9];
    const float* ln1s = (const float*)d_in[10];
    const float* ln1b = (const float*)d_in[11];
    const float* w_ir = (const float*)d_in[12];
    const float* b_ir = (const float*)d_in[13];
    const float* w_iz = (const float*)d_in[14];
    const float* b_iz = (const float*)d_in[15];
    const float* w_in = (const float*)d_in[16];
    const float* b_in = (const float*)d_in[17];
    const float* w_hr = (const float*)d_in[18];
    const float* w_hz = (const float*)d_in[19];
    const float* w_hn = (const float*)d_in[20];
    const float* b_hn = (const float*)d_in[21];
    const float* w_out = (const float*)d_in[22];
    const float* b_out = (const float*)d_in[23];

    float* out_hidden = (float*)d_out;
    float* out_q      = (float*)d_out + (size_t)BATCH * HID;

    float *S0, *S1, *Xg, *w0c, *w1c, *wgc;
    cudaGetSymbolAddress((void**)&S0,  g_S0);
    cudaGetSymbolAddress((void**)&S1,  g_S1);
    cudaGetSymbolAddress((void**)&Xg,  g_Xg);
    cudaGetSymbolAddress((void**)&w0c, g_w0c);
    cudaGetSymbolAddress((void**)&w1c, g_w1c);
    cudaGetSymbolAddress((void**)&wgc, g_wgc);

    const int gemm_smem = 3 * (GA_SZ + GB_SZ) * 4;                              // 105984 B
    const int scan_smem = (3 * 512 * 20 + 8 * ST_WARP + 128 * 52 + 64) * 4;     // 205056 B
    cudaFuncSetAttribute(gemm_db, cudaFuncAttributeMaxDynamicSharedMemorySize, gemm_smem);
    cudaFuncSetAttribute(scan_kernel, cudaFuncAttributeMaxDynamicSharedMemorySize, scan_smem);

    conv_tf32<<<(ROWS * HID / 4 + 255) / 256, 256>>>(obs, S1, ROWS * HID / 4);
    conv_tf32<<<256, 256>>>(w0, w0c, HID * HID / 4);
    conv_gates<<<1024, 256>>>(w_ir, w_iz, w_in, wgc);
    gemm_db<<<dim3(4, 512), 128, gemm_smem>>>(S1, w0c, S0, HID, HID);     // L0
    conv_tf32<<<256, 256>>>(w1, w1c, HID * HID / 4);
    mask0_kernel<<<(BATCH * HID) / 256, 256>>>(hidden, dones);
    ln_relu_kernel<<<ROWS, 128>>>(S0, S1, b0, ln0s, ln0b, w0, last_acts);
    gemm_db<<<dim3(4, 512), 128, gemm_smem>>>(S1, w1c, S0, HID, HID);     // L1
    ln_relu_kernel<<<ROWS, 128>>>(S0, S1, b1, ln1s, ln1b, nullptr, nullptr);
    gemm_db<<<dim3(12, 512), 128, gemm_smem>>>(S1, wgc, Xg, NG3, HID);    // gates

    scan_kernel<<<SC_CTAS, 256, scan_smem>>>(w_hr, w_hz, w_hn,
                                             b_ir, b_iz, b_in, b_hn,
                                             dones, out_hidden);

    qout_kernel<<<ROWS / 256, 256>>>(w_out, b_out, out_q);
}

// round 13
// speedup vs baseline: 1.2289x; 1.0140x over previous
#include <cuda_runtime.h>
#include <cuda_bf16.h>
#include <mma.h>
#include <math.h>
#include <stdint.h>

using namespace nvcuda;

#define T_STEPS 128
#define BATCH   512
#define HID     512
#define ADIM    18
#define ROWS    (T_STEPS * BATCH)   // 65536
#define NG3     (3 * HID)           // 1536
#define SC_CTAS 128
#define SC_GRP  32

// ---------------- scratch (static __device__, no allocs) ----------------
__device__ float g_S0[(size_t)ROWS * HID];
__device__ float g_S1[(size_t)ROWS * HID];
__device__ float g_Xg[(size_t)ROWS * NG3];
__device__ float g_htf[(size_t)BATCH * HID];   // tf32-RN carry (sole h state)
__device__ float g_w0c[HID * HID];
__device__ float g_w1c[HID * HID];
__device__ float g_wgc[HID * NG3];
__device__ unsigned int g_barg[4 * 32];        // 4 group barriers, 128B apart

// ---------------- cp.async helpers ----------------
__device__ __forceinline__ void cp16(uint32_t dst, const void* src) {
    asm volatile("cp.async.cg.shared.global [%0], [%1], 16;" :: "r"(dst), "l"(src));
}
#define CP_COMMIT() asm volatile("cp.async.commit_group;")
#define CP_WAIT0()  asm volatile("cp.async.wait_group 0;")
#define CP_WAIT1()  asm volatile("cp.async.wait_group 1;")

__device__ __forceinline__ float tf32r(float x) { return wmma::__float_to_tf32(x); }

__device__ __forceinline__ float tanh_apx(float x) {
    float y; asm("tanh.approx.f32 %0, %1;" : "=f"(y) : "f"(x)); return y;
}
__device__ __forceinline__ float sigm_apx(float x) { return 0.5f * tanh_apx(0.5f * x) + 0.5f; }

// ---------------- tf32-RN conversion passes ----------------
__global__ void conv_tf32(const float* __restrict__ s, float* __restrict__ d, int n4) {
    int i = blockIdx.x * 256 + threadIdx.x;
    if (i < n4) {
        float4 v = ((const float4*)s)[i];
        v.x = tf32r(v.x); v.y = tf32r(v.y); v.z = tf32r(v.z); v.w = tf32r(v.w);
        ((float4*)d)[i] = v;
    }
}

// interleave [w_ir | w_iz | w_in] column-wise into [512,1536] tf32
__global__ void conv_gates(const float* __restrict__ wir, const float* __restrict__ wiz,
                           const float* __restrict__ win, float* __restrict__ dst) {
    int i = blockIdx.x * 256 + threadIdx.x;   // 262144
    int k = i >> 9, c = i & 511;
    size_t o = (size_t)k * NG3 + c;
    dst[o]        = tf32r(wir[i]);
    dst[o + 512]  = tf32r(wiz[i]);
    dst[o + 1024] = tf32r(win[i]);
}

// ---------------- 3-stage TF32 GEMM: BM=128 BN=128 BK=32, 4 warps, 64x64 warp tile ----
#define GA_LD 36
#define GB_LD 132
#define GA_SZ (128 * GA_LD)
#define GB_SZ (32 * GB_LD)

__global__ void __launch_bounds__(128, 2) gemm_db(
    const float* __restrict__ A, const float* __restrict__ B,
    float* __restrict__ C, int N, int K)
{
    extern __shared__ float sm[];
    float* As = sm;
    float* Bs = sm + 3 * GA_SZ;

    const int tid = threadIdx.x;
    const int wid = tid >> 5;
    const size_t m0 = (size_t)blockIdx.y * 128;
    const int n0 = blockIdx.x * 128;
    const int wm = (wid >> 1) * 64;
    const int wn = (wid & 1) * 64;

    wmma::fragment<wmma::accumulator, 16, 16, 8, float> acc[4][4];
#pragma unroll
    for (int i = 0; i < 4; i++)
#pragma unroll
        for (int j = 0; j < 4; j++) wmma::fill_fragment(acc[i][j], 0.0f);

    const int NK = K / 32;

    auto load_stage = [&](int kc, int buf) {
        int k0 = kc * 32;
#pragma unroll
        for (int l = 0; l < 8; l++) {
            int f = tid + l * 128;
            int r = f >> 3, c = (f & 7) * 4;
            cp16((uint32_t)__cvta_generic_to_shared(As + buf * GA_SZ + r * GA_LD + c),
                 A + (m0 + r) * (size_t)K + k0 + c);
        }
#pragma unroll
        for (int l = 0; l < 8; l++) {
            int f = tid + l * 128;
            int r = f >> 5, c = (f & 31) * 4;
            cp16((uint32_t)__cvta_generic_to_shared(Bs + buf * GB_SZ + r * GB_LD + c),
                 B + (size_t)(k0 + r) * N + n0 + c);
        }
    };

    load_stage(0, 0); CP_COMMIT();
    load_stage(1, 1); CP_COMMIT();

    for (int kc = 0; kc < NK; kc++) {
        int buf = kc % 3;
        if (kc + 1 < NK) CP_WAIT1(); else CP_WAIT0();
        __syncthreads();
        if (kc + 2 < NK) { load_stage(kc + 2, (kc + 2) % 3); CP_COMMIT(); }
#pragma unroll
        for (int kk = 0; kk < 32; kk += 8) {
            wmma::fragment<wmma::matrix_a, 16, 16, 8, wmma::precision::tf32, wmma::row_major> af[4];
            wmma::fragment<wmma::matrix_b, 16, 16, 8, wmma::precision::tf32, wmma::row_major> bf[4];
#pragma unroll
            for (int i = 0; i < 4; i++)
                wmma::load_matrix_sync(af[i], As + buf * GA_SZ + (wm + 16 * i) * GA_LD + kk, GA_LD);
#pragma unroll
            for (int j = 0; j < 4; j++)
                wmma::load_matrix_sync(bf[j], Bs + buf * GB_SZ + kk * GB_LD + wn + 16 * j, GB_LD);
#pragma unroll
            for (int i = 0; i < 4; i++)
#pragma unroll
                for (int j = 0; j < 4; j++) wmma::mma_sync(acc[i][j], af[i], bf[j], acc[i][j]);
        }
    }
    __syncthreads();
#pragma unroll
    for (int i = 0; i < 4; i++)
#pragma unroll
        for (int j = 0; j < 4; j++)
            wmma::store_matrix_sync(C + (m0 + wm + 16 * i) * (size_t)N + n0 + wn + 16 * j,
                                    acc[i][j], N, wmma::mem_row_major);
}

// ---------------- LayerNorm(+bias,+one-hot) + ReLU, tf32-RN output ----------------
__global__ void __launch_bounds__(128) ln_relu_kernel(
    const float* __restrict__ in, float* __restrict__ out,
    const float* __restrict__ addb,
    const float* __restrict__ lns, const float* __restrict__ lnb,
    const float* __restrict__ w_oh, const int* __restrict__ acts)
{
    const int row = blockIdx.x;
    const int tid = threadIdx.x;
    const float* ip = in + (size_t)row * HID;

    float4 v = *(const float4*)(ip + tid * 4);
    float4 a = *(const float4*)(addb + tid * 4);
    v.x += a.x; v.y += a.y; v.z += a.z; v.w += a.w;
    if (w_oh) {
        const float* oh = w_oh + (size_t)(512 + acts[row]) * HID;
        float4 o = *(const float4*)(oh + tid * 4);
        v.x += o.x; v.y += o.y; v.z += o.z; v.w += o.w;
    }
    float sum = v.x + v.y + v.z + v.w;
    float sq  = v.x * v.x + v.y * v.y + v.z * v.z + v.w * v.w;

    __shared__ float red[8];
#pragma unroll
    for (int off = 16; off > 0; off >>= 1) {
        sum += __shfl_down_sync(0xFFFFFFFFu, sum, off);
        sq  += __shfl_down_sync(0xFFFFFFFFu, sq,  off);
    }
    if ((tid & 31) == 0) { red[tid >> 5] = sum; red[4 + (tid >> 5)] = sq; }
    __syncthreads();
    float ts = red[0] + red[1] + red[2] + red[3];
    float tq = red[4] + red[5] + red[6] + red[7];
    float mean = ts * (1.0f / HID);
    float var  = tq * (1.0f / HID) - mean * mean;
    float inv  = rsqrtf(var + 1e-6f);

    float4 sc = *(const float4*)(lns + tid * 4);
    float4 bb = *(const float4*)(lnb + tid * 4);
    float4 r;
    r.x = tf32r(fmaxf((v.x - mean) * inv * sc.x + bb.x, 0.0f));
    r.y = tf32r(fmaxf((v.y - mean) * inv * sc.y + bb.y, 0.0f));
    r.z = tf32r(fmaxf((v.z - mean) * inv * sc.z + bb.z, 0.0f));
    r.w = tf32r(fmaxf((v.w - mean) * inv * sc.w + bb.w, 0.0f));
    *(float4*)(out + (size_t)row * HID + tid * 4) = r;
}

// ---------------- initial done-mask (tf32 carry) ----------------
__global__ void mask0_kernel(const float* __restrict__ hidden_in,
                             const int* __restrict__ dones)
{
    int i = blockIdx.x * blockDim.x + threadIdx.x;
    int b = i >> 9;
    float v = dones[b] ? 0.0f : hidden_in[i];
    g_htf[i] = tf32r(v);
}

// ---------------- persistent fused GRU scan v6: float4 gates I/O ----------------
__device__ __forceinline__ void gsync_grp(int grp) {
    __threadfence();
    __syncthreads();
    if (threadIdx.x == 0) {
        unsigned int* ctr = &g_barg[grp * 32];
        unsigned int old = atomicAdd(ctr, 1u);
        unsigned int target = (old / SC_GRP + 1u) * SC_GRP;
        while (*((volatile unsigned int*)ctr) < target) { }
        __threadfence();
    }
    __syncthreads();
}

#define ST_LD 36
#define ST_BUF (16 * ST_LD)
#define ST_WARP (3 * ST_BUF)

__global__ void __launch_bounds__(256, 1) scan_kernel(
    const float* __restrict__ w_hr, const float* __restrict__ w_hz, const float* __restrict__ w_hn,
    const float* __restrict__ b_ir, const float* __restrict__ b_iz,
    const float* __restrict__ b_in, const float* __restrict__ b_hn,
    const int* __restrict__ dones,
    float* __restrict__ out_hidden)
{
    extern __shared__ float ssm[];
    float* Wp = ssm;                      // 3 * 512 * 20
    float* At = Wp + 3 * 512 * 20;        // 8 * ST_WARP
    float* Sc = At + 8 * ST_WARP;         // 128 * 52
    float* Bb = Sc + 128 * 52;            // 64

    const int tid  = threadIdx.x;
    const int wid  = tid >> 5;
    const int lane = tid & 31;
    const int bx   = blockIdx.x;
    const int c0   = (bx & 31) * 16;
    const int grp  = bx >> 5;
    const int m0   = grp * 128;

    {
        const float* Ws[3] = {w_hr, w_hz, w_hn};
#pragma unroll
        for (int g = 0; g < 3; g++) {
            for (int i4 = tid; i4 < 2048; i4 += 256) {
                int k = i4 >> 2, cc = (i4 & 3) * 4;
                float4 v = *(const float4*)(Ws[g] + (size_t)k * HID + c0 + cc);
                float* d = Wp + g * (512 * 20) + k * 20 + cc;
                d[0] = tf32r(v.x); d[1] = tf32r(v.y); d[2] = tf32r(v.z); d[3] = tf32r(v.w);
            }
        }
        if (tid < 16) {
            Bb[tid]      = b_ir[c0 + tid];
            Bb[16 + tid] = b_iz[c0 + tid];
            Bb[32 + tid] = b_in[c0 + tid];
            Bb[48 + tid] = b_hn[c0 + tid];
        }
    }
    __syncthreads();

    const int wrow = wid * 16;
    float* Wstrip = At + wid * ST_WARP;

    auto load_strip = [&](int k0, int buf) {
        float* dst = Wstrip + buf * ST_BUF;
#pragma unroll
        for (int i = 0; i < 4; i++) {
            int f = lane + i * 32;
            int r = f >> 3, c = (f & 7) * 4;
            cp16((uint32_t)__cvta_generic_to_shared(dst + r * ST_LD + c),
                 g_htf + (size_t)(m0 + wrow + r) * HID + k0 + c);
        }
    };

    // element mapping: lane owns 2 rows x 4 consecutive cols
    const int rpair = lane >> 2;          // 0..7 -> rows rpair*2, rpair*2+1
    const int col4  = (lane & 3) * 4;     // 0,4,8,12
    const int cg0   = c0 + col4;

    // step-invariant gate biases (hoisted)
    const float4 bir4 = *(const float4*)(Bb + col4);
    const float4 biz4 = *(const float4*)(Bb + 16 + col4);
    const float4 bin4 = *(const float4*)(Bb + 32 + col4);
    const float4 bhn4 = *(const float4*)(Bb + 48 + col4);

    for (int t = 0; t < T_STEPS; t++) {
        const bool lastt = (t == T_STEPS - 1);

        float4 pxr[2], pxz[2], pxn[2], ph4[2];
        int pdn[2], bgr[2];
#pragma unroll
        for (int rr = 0; rr < 2; rr++) bgr[rr] = m0 + wrow + rpair * 2 + rr;

        // ---- prefetch row 0 (latency hidden under GEMM half 1) ----
        {
            const float* xg = g_Xg + ((size_t)t * BATCH + bgr[0]) * NG3 + cg0;
            pxr[0] = __ldcg((const float4*)xg);
            pxz[0] = __ldcg((const float4*)(xg + 512));
            pxn[0] = __ldcg((const float4*)(xg + 1024));
            ph4[0] = *(const float4*)(g_htf + (size_t)bgr[0] * HID + cg0);
            pdn[0] = lastt ? 0 : dones[(t + 1) * BATCH + bgr[0]];
        }

        wmma::fragment<wmma::accumulator, 16, 16, 8, float> acc[3];
#pragma unroll
        for (int g = 0; g < 3; g++) wmma::fill_fragment(acc[g], 0.0f);

        load_strip(0, 0); CP_COMMIT();
        load_strip(32, 1); CP_COMMIT();

        // ---- kc half 1: 0..7 ----
        for (int kc = 0; kc < 8; kc++) {
            int buf = kc % 3;
            CP_WAIT1();
            __syncwarp();
            load_strip((kc + 2) * 32, (kc + 2) % 3); CP_COMMIT();
            int k0 = kc * 32;
            const float* sa = Wstrip + buf * ST_BUF;
#pragma unroll
            for (int kk = 0; kk < 32; kk += 8) {
                wmma::fragment<wmma::matrix_a, 16, 16, 8, wmma::precision::tf32, wmma::row_major> af;
                wmma::load_matrix_sync(af, sa + kk, ST_LD);
#pragma unroll
                for (int g = 0; g < 3; g++) {
                    wmma::fragment<wmma::matrix_b, 16, 16, 8, wmma::precision::tf32, wmma::row_major> bf;
                    wmma::load_matrix_sync(bf, Wp + g * (512 * 20) + (k0 + kk) * 20, 20);
                    wmma::mma_sync(acc[g], af, bf, acc[g]);
                }
            }
        }

        // ---- prefetch row 1 ----
        {
            const float* xg = g_Xg + ((size_t)t * BATCH + bgr[1]) * NG3 + cg0;
            pxr[1] = __ldcg((const float4*)xg);
            pxz[1] = __ldcg((const float4*)(xg + 512));
            pxn[1] = __ldcg((const float4*)(xg + 1024));
            ph4[1] = *(const float4*)(g_htf + (size_t)bgr[1] * HID + cg0);
            pdn[1] = lastt ? 0 : dones[(t + 1) * BATCH + bgr[1]];
        }

        // ---- kc half 2: 8..15 ----
        for (int kc = 8; kc < 16; kc++) {
            int buf = kc % 3;
            if (kc + 1 < 16) CP_WAIT1(); else CP_WAIT0();
            __syncwarp();
            if (kc + 2 < 16) { load_strip((kc + 2) * 32, (kc + 2) % 3); CP_COMMIT(); }
            int k0 = kc * 32;
            const float* sa = Wstrip + buf * ST_BUF;
#pragma unroll
            for (int kk = 0; kk < 32; kk += 8) {
                wmma::fragment<wmma::matrix_a, 16, 16, 8, wmma::precision::tf32, wmma::row_major> af;
                wmma::load_matrix_sync(af, sa + kk, ST_LD);
#pragma unroll
                for (int g = 0; g < 3; g++) {
                    wmma::fragment<wmma::matrix_b, 16, 16, 8, wmma::precision::tf32, wmma::row_major> bf;
                    wmma::load_matrix_sync(bf, Wp + g * (512 * 20) + (k0 + kk) * 20, 20);
                    wmma::mma_sync(acc[g], af, bf, acc[g]);
                }
            }
        }

        // spill accs to this warp's private Sc slab
#pragma unroll
        for (int g = 0; g < 3; g++)
            wmma::store_matrix_sync(Sc + wrow * 52 + g * 16, acc[g], 52, wmma::mem_row_major);
        __syncwarp();

        // ---- gates: float4 per row ----
#pragma unroll
        for (int rr = 0; rr < 2; rr++) {
            int row = wrow + rpair * 2 + rr;
            int bg = bgr[rr];
            const float* sc = Sc + row * 52;
            float4 hgr = *(const float4*)(sc + col4);
            float4 hgz = *(const float4*)(sc + 16 + col4);
            float4 hgn = *(const float4*)(sc + 32 + col4);
            float4 px = pxr[rr], pz = pxz[rr], pn = pxn[rr], hh = ph4[rr];

            float4 hn4;
            {
                float r0 = sigm_apx(px.x + bir4.x + hgr.x);
                float z0 = sigm_apx(pz.x + biz4.x + hgz.x);
                float n0 = tanh_apx(pn.x + bin4.x + r0 * (hgn.x + bhn4.x));
                hn4.x = (1.0f - z0) * n0 + z0 * hh.x;
                float r1 = sigm_apx(px.y + bir4.y + hgr.y);
                float z1 = sigm_apx(pz.y + biz4.y + hgz.y);
                float n1 = tanh_apx(pn.y + bin4.y + r1 * (hgn.y + bhn4.y));
                hn4.y = (1.0f - z1) * n1 + z1 * hh.y;
                float r2 = sigm_apx(px.z + bir4.z + hgr.z);
                float z2 = sigm_apx(pz.z + biz4.z + hgz.z);
                float n2 = tanh_apx(pn.z + bin4.z + r2 * (hgn.z + bhn4.z));
                hn4.z = (1.0f - z2) * n2 + z2 * hh.z;
                float r3 = sigm_apx(px.w + bir4.w + hgr.w);
                float z3 = sigm_apx(pz.w + biz4.w + hgz.w);
                float n3 = tanh_apx(pn.w + bin4.w + r3 * (hgn.w + bhn4.w));
                hn4.w = (1.0f - z3) * n3 + z3 * hh.w;
            }
            *(float4*)(g_S0 + ((size_t)t * BATCH + bg) * HID + cg0) = hn4;
            float4 hm4;
            if (pdn[rr]) hm4 = make_float4(0.f, 0.f, 0.f, 0.f);
            else hm4 = make_float4(tf32r(hn4.x), tf32r(hn4.y), tf32r(hn4.z), tf32r(hn4.w));
            *(float4*)(g_htf + (size_t)bg * HID + cg0) = hm4;
            if (lastt) *(float4*)(out_hidden + (size_t)bg * HID + cg0) = hn4;
        }

        if (!lastt) gsync_grp(grp);
    }
}

// ---------------- output head ----------------
__global__ void __launch_bounds__(256) qout_kernel(
    const float* __restrict__ w_out, const float* __restrict__ b_out,
    float* __restrict__ q)
{
    __shared__ float ws[HID * ADIM];
    for (int i = threadIdx.x; i < HID * ADIM; i += 256) ws[i] = w_out[i];
    __syncthreads();

    const size_t row = (size_t)blockIdx.x * 256 + threadIdx.x;
    const float* y = g_S0 + row * HID;
    float acc[ADIM];
#pragma unroll
    for (int a = 0; a < ADIM; a++) acc[a] = b_out[a];

    for (int c = 0; c < HID; c += 4) {
        float4 v = *(const float4*)(y + c);
        float yv[4] = {v.x, v.y, v.z, v.w};
#pragma unroll
        for (int j = 0; j < 4; j++)
#pragma unroll
            for (int a = 0; a < ADIM; a++)
                acc[a] = fmaf(yv[j], ws[(c + j) * ADIM + a], acc[a]);
    }
    float* qp = q + row * ADIM;
#pragma unroll
    for (int a = 0; a < ADIM; a++) qp[a] = acc[a];
}

// ---------------- launch ----------------
extern "C" void kernel_launch(void* const* d_in, const int* in_sizes, int n_in,
                              void* d_out, int out_size)
{
    const float* hidden    = (const float*)d_in[0];
    const float* obs       = (const float*)d_in[1];
    const int*   dones     = (const int*)d_in[2];
    const int*   last_acts = (const int*)d_in[3];
    const float* w0   = (const float*)d_in[4];
    const float* b0   = (const float*)d_in[5];
    const float* ln0s = (const float*)d_in[6];
    const float* ln0b = (const float*)d_in[7];
    const float* w1   = (const float*)d_in[8];
    const float* b1   = (const float*)d_in[9];
    const float* ln1s = (const float*)d_in[10];
    const float* ln1b = (const float*)d_in[11];
    const float* w_ir = (const float*)d_in[12];
    const float* b_ir = (const float*)d_in[13];
    const float* w_iz = (const float*)d_in[14];
    const float* b_iz = (const float*)d_in[15];
    const float* w_in = (const float*)d_in[16];
    const float* b_in = (const float*)d_in[17];
    const float* w_hr = (const float*)d_in[18];
    const float* w_hz = (const float*)d_in[19];
    const float* w_hn = (const float*)d_in[20];
    const float* b_hn = (const float*)d_in[21];
    const float* w_out = (const float*)d_in[22];
    const float* b_out = (const float*)d_in[23];

    float* out_hidden = (float*)d_out;
    float* out_q      = (float*)d_out + (size_t)BATCH * HID;

    float *S0, *S1, *Xg, *w0c, *w1c, *wgc;
    cudaGetSymbolAddress((void**)&S0,  g_S0);
    cudaGetSymbolAddress((void**)&S1,  g_S1);
    cudaGetSymbolAddress((void**)&Xg,  g_Xg);
    cudaGetSymbolAddress((void**)&w0c, g_w0c);
    cudaGetSymbolAddress((void**)&w1c, g_w1c);
    cudaGetSymbolAddress((void**)&wgc, g_wgc);

    const int gemm_smem = 3 * (GA_SZ + GB_SZ) * 4;                              // 105984 B
    const int scan_smem = (3 * 512 * 20 + 8 * ST_WARP + 128 * 52 + 64) * 4;     // 205056 B
    cudaFuncSetAttribute(gemm_db, cudaFuncAttributeMaxDynamicSharedMemorySize, gemm_smem);
    cudaFuncSetAttribute(scan_kernel, cudaFuncAttributeMaxDynamicSharedMemorySize, scan_smem);

    conv_tf32<<<(ROWS * HID / 4 + 255) / 256, 256>>>(obs, S1, ROWS * HID / 4);
    conv_tf32<<<256, 256>>>(w0, w0c, HID * HID / 4);
    conv_gates<<<1024, 256>>>(w_ir, w_iz, w_in, wgc);
    gemm_db<<<dim3(4, 512), 128, gemm_smem>>>(S1, w0c, S0, HID, HID);     // L0
    conv_tf32<<<256, 256>>>(w1, w1c, HID * HID / 4);
    mask0_kernel<<<(BATCH * HID) / 256, 256>>>(hidden, dones);
    ln_relu_kernel<<<ROWS, 128>>>(S0, S1, b0, ln0s, ln0b, w0, last_acts);
    gemm_db<<<dim3(4, 512), 128, gemm_smem>>>(S1, w1c, S0, HID, HID);     // L1
    ln_relu_kernel<<<ROWS, 128>>>(S0, S1, b1, ln1s, ln1b, nullptr, nullptr);
    gemm_db<<<dim3(12, 512), 128, gemm_smem>>>(S1, wgc, Xg, NG3, HID);    // gates

    scan_kernel<<<SC_CTAS, 256, scan_smem>>>(w_hr, w_hz, w_hn,
                                             b_ir, b_iz, b_in, b_hn,
                                             dones, out_hidden);

    qout_kernel<<<ROWS / 256, 256>>>(w_out, b_out, out_q);
}

// round 15
// speedup vs baseline: 1.5673x; 1.2753x over previous
#include <cuda_runtime.h>
#include <cuda_bf16.h>
#include <mma.h>
#include <math.h>
#include <stdint.h>

using namespace nvcuda;

#define T_STEPS 128
#define BATCH   512
#define HID     512
#define ADIM    18
#define ROWS    (T_STEPS * BATCH)   // 65536
#define NG3     (3 * HID)           // 1536
#define SC_CTAS 128
#define SC_GRP  32

// ---------------- scratch (static __device__, no allocs) ----------------
__device__ float g_S0[(size_t)ROWS * HID];
__device__ float g_S1[(size_t)ROWS * HID];
__device__ float g_Xg[(size_t)ROWS * NG3];
__device__ float g_htf[(size_t)BATCH * HID];   // tf32-RN carry (sole h state)
__device__ float g_w0c[HID * HID];
__device__ float g_w1c[HID * HID];
__device__ float g_wgc[HID * NG3];
__device__ unsigned int g_barg[4 * 32];        // 4 group barriers, 128B apart

// ---------------- cp.async helpers ----------------
__device__ __forceinline__ void cp16(uint32_t dst, const void* src) {
    asm volatile("cp.async.cg.shared.global [%0], [%1], 16;" :: "r"(dst), "l"(src));
}
#define CP_COMMIT() asm volatile("cp.async.commit_group;")
#define CP_WAIT0()  asm volatile("cp.async.wait_group 0;")
#define CP_WAIT1()  asm volatile("cp.async.wait_group 1;")

__device__ __forceinline__ float tf32r(float x) { return wmma::__float_to_tf32(x); }

__device__ __forceinline__ float tanh_apx(float x) {
    float y; asm("tanh.approx.f32 %0, %1;" : "=f"(y) : "f"(x)); return y;
}
__device__ __forceinline__ float sigm_apx(float x) { return 0.5f * tanh_apx(0.5f * x) + 0.5f; }

// raw tf32 mma: D += A(m16k8,row) * B(k8n8,col)
__device__ __forceinline__ void mma_tf32(float* d, const uint32_t* a, const uint32_t* b) {
    asm volatile(
        "mma.sync.aligned.m16n8k8.row.col.f32.tf32.tf32.f32 "
        "{%0,%1,%2,%3}, {%4,%5,%6,%7}, {%8,%9}, {%0,%1,%2,%3};"
        : "+f"(d[0]), "+f"(d[1]), "+f"(d[2]), "+f"(d[3])
        : "r"(a[0]), "r"(a[1]), "r"(a[2]), "r"(a[3]), "r"(b[0]), "r"(b[1]));
}

// ---------------- tf32-RN conversion passes ----------------
__global__ void conv_tf32(const float* __restrict__ s, float* __restrict__ d, int n4) {
    int i = blockIdx.x * 256 + threadIdx.x;
    if (i < n4) {
        float4 v = ((const float4*)s)[i];
        v.x = tf32r(v.x); v.y = tf32r(v.y); v.z = tf32r(v.z); v.w = tf32r(v.w);
        ((float4*)d)[i] = v;
    }
}

// interleave [w_ir | w_iz | w_in] column-wise into [512,1536] tf32
__global__ void conv_gates(const float* __restrict__ wir, const float* __restrict__ wiz,
                           const float* __restrict__ win, float* __restrict__ dst) {
    int i = blockIdx.x * 256 + threadIdx.x;   // 262144
    int k = i >> 9, c = i & 511;
    size_t o = (size_t)k * NG3 + c;
    dst[o]        = tf32r(wir[i]);
    dst[o + 512]  = tf32r(wiz[i]);
    dst[o + 1024] = tf32r(win[i]);
}

// ---------------- 3-stage TF32 GEMM: BM=128 BN=128 BK=32, 4 warps, 64x64 warp tile ----
#define GA_LD 36
#define GB_LD 132
#define GA_SZ (128 * GA_LD)
#define GB_SZ (32 * GB_LD)

__global__ void __launch_bounds__(128, 2) gemm_db(
    const float* __restrict__ A, const float* __restrict__ B,
    float* __restrict__ C, int N, int K)
{
    extern __shared__ float sm[];
    float* As = sm;
    float* Bs = sm + 3 * GA_SZ;

    const int tid = threadIdx.x;
    const int wid = tid >> 5;
    const size_t m0 = (size_t)blockIdx.y * 128;
    const int n0 = blockIdx.x * 128;
    const int wm = (wid >> 1) * 64;
    const int wn = (wid & 1) * 64;

    wmma::fragment<wmma::accumulator, 16, 16, 8, float> acc[4][4];
#pragma unroll
    for (int i = 0; i < 4; i++)
#pragma unroll
        for (int j = 0; j < 4; j++) wmma::fill_fragment(acc[i][j], 0.0f);

    const int NK = K / 32;

    auto load_stage = [&](int kc, int buf) {
        int k0 = kc * 32;
#pragma unroll
        for (int l = 0; l < 8; l++) {
            int f = tid + l * 128;
            int r = f >> 3, c = (f & 7) * 4;
            cp16((uint32_t)__cvta_generic_to_shared(As + buf * GA_SZ + r * GA_LD + c),
                 A + (m0 + r) * (size_t)K + k0 + c);
        }
#pragma unroll
        for (int l = 0; l < 8; l++) {
            int f = tid + l * 128;
            int r = f >> 5, c = (f & 31) * 4;
            cp16((uint32_t)__cvta_generic_to_shared(Bs + buf * GB_SZ + r * GB_LD + c),
                 B + (size_t)(k0 + r) * N + n0 + c);
        }
    };

    load_stage(0, 0); CP_COMMIT();
    load_stage(1, 1); CP_COMMIT();

    for (int kc = 0; kc < NK; kc++) {
        int buf = kc % 3;
        if (kc + 1 < NK) CP_WAIT1(); else CP_WAIT0();
        __syncthreads();
        if (kc + 2 < NK) { load_stage(kc + 2, (kc + 2) % 3); CP_COMMIT(); }
#pragma unroll
        for (int kk = 0; kk < 32; kk += 8) {
            wmma::fragment<wmma::matrix_a, 16, 16, 8, wmma::precision::tf32, wmma::row_major> af[4];
            wmma::fragment<wmma::matrix_b, 16, 16, 8, wmma::precision::tf32, wmma::row_major> bf[4];
#pragma unroll
            for (int i = 0; i < 4; i++)
                wmma::load_matrix_sync(af[i], As + buf * GA_SZ + (wm + 16 * i) * GA_LD + kk, GA_LD);
#pragma unroll
            for (int j = 0; j < 4; j++)
                wmma::load_matrix_sync(bf[j], Bs + buf * GB_SZ + kk * GB_LD + wn + 16 * j, GB_LD);
#pragma unroll
            for (int i = 0; i < 4; i++)
#pragma unroll
                for (int j = 0; j < 4; j++) wmma::mma_sync(acc[i][j], af[i], bf[j], acc[i][j]);
        }
    }
    __syncthreads();
#pragma unroll
    for (int i = 0; i < 4; i++)
#pragma unroll
        for (int j = 0; j < 4; j++)
            wmma::store_matrix_sync(C + (m0 + wm + 16 * i) * (size_t)N + n0 + wn + 16 * j,
                                    acc[i][j], N, wmma::mem_row_major);
}

// ---------------- LayerNorm(+bias,+one-hot) + ReLU, tf32-RN output ----------------
__global__ void __launch_bounds__(128) ln_relu_kernel(
    const float* __restrict__ in, float* __restrict__ out,
    const float* __restrict__ addb,
    const float* __restrict__ lns, const float* __restrict__ lnb,
    const float* __restrict__ w_oh, const int* __restrict__ acts)
{
    const int row = blockIdx.x;
    const int tid = threadIdx.x;
    const float* ip = in + (size_t)row * HID;

    float4 v = *(const float4*)(ip + tid * 4);
    float4 a = *(const float4*)(addb + tid * 4);
    v.x += a.x; v.y += a.y; v.z += a.z; v.w += a.w;
    if (w_oh) {
        const float* oh = w_oh + (size_t)(512 + acts[row]) * HID;
        float4 o = *(const float4*)(oh + tid * 4);
        v.x += o.x; v.y += o.y; v.z += o.z; v.w += o.w;
    }
    float sum = v.x + v.y + v.z + v.w;
    float sq  = v.x * v.x + v.y * v.y + v.z * v.z + v.w * v.w;

    __shared__ float red[8];
#pragma unroll
    for (int off = 16; off > 0; off >>= 1) {
        sum += __shfl_down_sync(0xFFFFFFFFu, sum, off);
        sq  += __shfl_down_sync(0xFFFFFFFFu, sq,  off);
    }
    if ((tid & 31) == 0) { red[tid >> 5] = sum; red[4 + (tid >> 5)] = sq; }
    __syncthreads();
    float ts = red[0] + red[1] + red[2] + red[3];
    float tq = red[4] + red[5] + red[6] + red[7];
    float mean = ts * (1.0f / HID);
    float var  = tq * (1.0f / HID) - mean * mean;
    float inv  = rsqrtf(var + 1e-6f);

    float4 sc = *(const float4*)(lns + tid * 4);
    float4 bb = *(const float4*)(lnb + tid * 4);
    float4 r;
    r.x = tf32r(fmaxf((v.x - mean) * inv * sc.x + bb.x, 0.0f));
    r.y = tf32r(fmaxf((v.y - mean) * inv * sc.y + bb.y, 0.0f));
    r.z = tf32r(fmaxf((v.z - mean) * inv * sc.z + bb.z, 0.0f));
    r.w = tf32r(fmaxf((v.w - mean) * inv * sc.w + bb.w, 0.0f));
    *(float4*)(out + (size_t)row * HID + tid * 4) = r;
}

// ---------------- initial done-mask (tf32 carry) ----------------
__global__ void mask0_kernel(const float* __restrict__ hidden_in,
                             const int* __restrict__ dones)
{
    int i = blockIdx.x * blockDim.x + threadIdx.x;
    int b = i >> 9;
    float v = dones[b] ? 0.0f : hidden_in[i];
    g_htf[i] = tf32r(v);
}

// ---------------- persistent fused GRU scan v7: raw mma, register-resident gates ----
__device__ __forceinline__ void gsync_grp(int grp) {
    __threadfence();
    __syncthreads();
    if (threadIdx.x == 0) {
        unsigned int* ctr = &g_barg[grp * 32];
        unsigned int old = atomicAdd(ctr, 1u);
        unsigned int target = (old / SC_GRP + 1u) * SC_GRP;
        while (*((volatile unsigned int*)ctr) < target) { }
        __threadfence();
    }
    __syncthreads();
}

#define ST_LD 36
#define ST_BUF (16 * ST_LD)
#define ST_WARP (3 * ST_BUF)
#define WP_LD 24

__global__ void __launch_bounds__(256, 1) scan_kernel(
    const float* __restrict__ w_hr, const float* __restrict__ w_hz, const float* __restrict__ w_hn,
    const float* __restrict__ b_ir, const float* __restrict__ b_iz,
    const float* __restrict__ b_in, const float* __restrict__ b_hn,
    const int* __restrict__ dones,
    float* __restrict__ out_hidden)
{
    extern __shared__ float ssm[];
    float* Wp = ssm;                      // 3 * 512 * 24 = 36864
    float* At = Wp + 3 * 512 * WP_LD;     // 8 * ST_WARP  = 13824
    float* Bb = At + 8 * ST_WARP;         // 64

    const int tid  = threadIdx.x;
    const int wid  = tid >> 5;
    const int lane = tid & 31;
    const int bx   = blockIdx.x;
    const int c0   = (bx & 31) * 16;
    const int grp  = bx >> 5;
    const int m0   = grp * 128;

    // prologue: weight panels [512 x 16] x3 as tf32-RN (LD=24, conflict-free B loads)
    {
        const float* Ws[3] = {w_hr, w_hz, w_hn};
#pragma unroll
        for (int g = 0; g < 3; g++) {
            for (int i4 = tid; i4 < 2048; i4 += 256) {
                int k = i4 >> 2, cc = (i4 & 3) * 4;
                float4 v = *(const float4*)(Ws[g] + (size_t)k * HID + c0 + cc);
                float* d = Wp + g * (512 * WP_LD) + k * WP_LD + cc;
                d[0] = tf32r(v.x); d[1] = tf32r(v.y); d[2] = tf32r(v.z); d[3] = tf32r(v.w);
            }
        }
        if (tid < 16) {
            Bb[tid]      = b_ir[c0 + tid];
            Bb[16 + tid] = b_iz[c0 + tid];
            Bb[32 + tid] = b_in[c0 + tid];
            Bb[48 + tid] = b_hn[c0 + tid];
        }
    }
    __syncthreads();

    const int wrow = wid * 16;
    float* Wstrip = At + wid * ST_WARP;

    auto load_strip = [&](int k0, int buf) {
        float* dst = Wstrip + buf * ST_BUF;
#pragma unroll
        for (int i = 0; i < 4; i++) {
            int f = lane + i * 32;
            int r = f >> 3, c = (f & 7) * 4;
            cp16((uint32_t)__cvta_generic_to_shared(dst + r * ST_LD + c),
                 g_htf + (size_t)(m0 + wrow + r) * HID + k0 + c);
        }
    };

    // mma lane coords
    const int grp4 = lane >> 2;     // 0..7
    const int tid4 = lane & 3;      // 0..3

    // thread's output coords: rows wrow+grp4, wrow+grp4+8; cols c0 + nt*8 + 2*tid4 (+1)
    int bgr[2];
    bgr[0] = m0 + wrow + grp4;
    bgr[1] = m0 + wrow + grp4 + 8;
    int cloc[2];                      // local col (within 16) of float2 start
    cloc[0] = 2 * tid4;
    cloc[1] = 8 + 2 * tid4;

    // hoisted biases (float2 per ntile)
    float2 bir[2], biz[2], bin[2], bhn[2];
#pragma unroll
    for (int nt = 0; nt < 2; nt++) {
        bir[nt] = *(const float2*)(Bb + cloc[nt]);
        biz[nt] = *(const float2*)(Bb + 16 + cloc[nt]);
        bin[nt] = *(const float2*)(Bb + 32 + cloc[nt]);
        bhn[nt] = *(const float2*)(Bb + 48 + cloc[nt]);
    }

    for (int t = 0; t < T_STEPS; t++) {
        const bool lastt = (t == T_STEPS - 1);

        float2 pxr[2][2], pxz[2][2], pxn[2][2], ph2[2][2];   // [row][nt]
        int pdn[2];

        // ---- prefetch row 0 ----
        {
            const float* xg = g_Xg + ((size_t)t * BATCH + bgr[0]) * NG3 + c0;
#pragma unroll
            for (int nt = 0; nt < 2; nt++) {
                pxr[0][nt] = __ldcg((const float2*)(xg + cloc[nt]));
                pxz[0][nt] = __ldcg((const float2*)(xg + 512 + cloc[nt]));
                pxn[0][nt] = __ldcg((const float2*)(xg + 1024 + cloc[nt]));
                ph2[0][nt] = *(const float2*)(g_htf + (size_t)bgr[0] * HID + c0 + cloc[nt]);
            }
            pdn[0] = lastt ? 0 : dones[(t + 1) * BATCH + bgr[0]];
        }

        float acc[3][2][4];
#pragma unroll
        for (int g = 0; g < 3; g++)
#pragma unroll
            for (int nt = 0; nt < 2; nt++)
#pragma unroll
                for (int e = 0; e < 4; e++) acc[g][nt][e] = 0.0f;

        load_strip(0, 0); CP_COMMIT();
        load_strip(32, 1); CP_COMMIT();

        // ---- kc half 1: 0..7 ----
        for (int kc = 0; kc < 8; kc++) {
            int buf = kc % 3;
            CP_WAIT1();
            __syncwarp();
            load_strip((kc + 2) * 32, (kc + 2) % 3); CP_COMMIT();
            int k0g = kc * 32;
            const float* sa = Wstrip + buf * ST_BUF;
#pragma unroll
            for (int kk = 0; kk < 32; kk += 8) {
                uint32_t a[4];
                a[0] = __float_as_uint(sa[grp4 * ST_LD + kk + tid4]);
                a[1] = __float_as_uint(sa[(grp4 + 8) * ST_LD + kk + tid4]);
                a[2] = __float_as_uint(sa[grp4 * ST_LD + kk + tid4 + 4]);
                a[3] = __float_as_uint(sa[(grp4 + 8) * ST_LD + kk + tid4 + 4]);
#pragma unroll
                for (int g = 0; g < 3; g++) {
                    const float* wb = Wp + g * (512 * WP_LD) + (size_t)(k0g + kk + tid4) * WP_LD;
#pragma unroll
                    for (int nt = 0; nt < 2; nt++) {
                        uint32_t b[2];
                        b[0] = __float_as_uint(wb[nt * 8 + grp4]);
                        b[1] = __float_as_uint(wb[4 * WP_LD + nt * 8 + grp4]);
                        mma_tf32(acc[g][nt], a, b);
                    }
                }
            }
        }

        // ---- prefetch row 1 ----
        {
            const float* xg = g_Xg + ((size_t)t * BATCH + bgr[1]) * NG3 + c0;
#pragma unroll
            for (int nt = 0; nt < 2; nt++) {
                pxr[1][nt] = __ldcg((const float2*)(xg + cloc[nt]));
                pxz[1][nt] = __ldcg((const float2*)(xg + 512 + cloc[nt]));
                pxn[1][nt] = __ldcg((const float2*)(xg + 1024 + cloc[nt]));
                ph2[1][nt] = *(const float2*)(g_htf + (size_t)bgr[1] * HID + c0 + cloc[nt]);
            }
            pdn[1] = lastt ? 0 : dones[(t + 1) * BATCH + bgr[1]];
        }

        // ---- kc half 2: 8..15 ----
        for (int kc = 8; kc < 16; kc++) {
            int buf = kc % 3;
            if (kc + 1 < 16) CP_WAIT1(); else CP_WAIT0();
            __syncwarp();
            if (kc + 2 < 16) { load_strip((kc + 2) * 32, (kc + 2) % 3); CP_COMMIT(); }
            int k0g = kc * 32;
            const float* sa = Wstrip + buf * ST_BUF;
#pragma unroll
            for (int kk = 0; kk < 32; kk += 8) {
                uint32_t a[4];
                a[0] = __float_as_uint(sa[grp4 * ST_LD + kk + tid4]);
                a[1] = __float_as_uint(sa[(grp4 + 8) * ST_LD + kk + tid4]);
                a[2] = __float_as_uint(sa[grp4 * ST_LD + kk + tid4 + 4]);
                a[3] = __float_as_uint(sa[(grp4 + 8) * ST_LD + kk + tid4 + 4]);
#pragma unroll
                for (int g = 0; g < 3; g++) {
                    const float* wb = Wp + g * (512 * WP_LD) + (size_t)(k0g + kk + tid4) * WP_LD;
#pragma unroll
                    for (int nt = 0; nt < 2; nt++) {
                        uint32_t b[2];
                        b[0] = __float_as_uint(wb[nt * 8 + grp4]);
                        b[1] = __float_as_uint(wb[4 * WP_LD + nt * 8 + grp4]);
                        mma_tf32(acc[g][nt], a, b);
                    }
                }
            }
        }

        // ---- gates: direct from accumulator registers ----
        // acc[g][nt][0..1] -> row bgr[0], cols cloc[nt], +1 ; acc[g][nt][2..3] -> row bgr[1]
#pragma unroll
        for (int rr = 0; rr < 2; rr++) {
            int bg = bgr[rr];
            size_t s0row = ((size_t)t * BATCH + bg) * HID + c0;
            size_t hrow  = (size_t)bg * HID + c0;
#pragma unroll
            for (int nt = 0; nt < 2; nt++) {
                float hgr0 = acc[0][nt][2 * rr],     hgr1 = acc[0][nt][2 * rr + 1];
                float hgz0 = acc[1][nt][2 * rr],     hgz1 = acc[1][nt][2 * rr + 1];
                float hgn0 = acc[2][nt][2 * rr],     hgn1 = acc[2][nt][2 * rr + 1];
                float2 px = pxr[rr][nt], pz = pxz[rr][nt], pn = pxn[rr][nt], hh = ph2[rr][nt];

                float r0 = sigm_apx(px.x + bir[nt].x + hgr0);
                float z0 = sigm_apx(pz.x + biz[nt].x + hgz0);
                float n0 = tanh_apx(pn.x + bin[nt].x + r0 * (hgn0 + bhn[nt].x));
                float h0 = (1.0f - z0) * n0 + z0 * hh.x;
                float r1 = sigm_apx(px.y + bir[nt].y + hgr1);
                float z1 = sigm_apx(pz.y + biz[nt].y + hgz1);
                float n1 = tanh_apx(pn.y + bin[nt].y + r1 * (hgn1 + bhn[nt].y));
                float h1 = (1.0f - z1) * n1 + z1 * hh.y;

                float2 hn2 = make_float2(h0, h1);
                *(float2*)(g_S0 + s0row + cloc[nt]) = hn2;
                float2 hm2 = pdn[rr] ? make_float2(0.f, 0.f)
                                     : make_float2(tf32r(h0), tf32r(h1));
                *(float2*)(g_htf + hrow + cloc[nt]) = hm2;
                if (lastt) *(float2*)(out_hidden + hrow + cloc[nt]) = hn2;
            }
        }

        if (!lastt) gsync_grp(grp);
    }
}

// ---------------- output head ----------------
__global__ void __launch_bounds__(256) qout_kernel(
    const float* __restrict__ w_out, const float* __restrict__ b_out,
    float* __restrict__ q)
{
    __shared__ float ws[HID * ADIM];
    for (int i = threadIdx.x; i < HID * ADIM; i += 256) ws[i] = w_out[i];
    __syncthreads();

    const size_t row = (size_t)blockIdx.x * 256 + threadIdx.x;
    const float* y = g_S0 + row * HID;
    float acc[ADIM];
#pragma unroll
    for (int a = 0; a < ADIM; a++) acc[a] = b_out[a];

    for (int c = 0; c < HID; c += 4) {
        float4 v = *(const float4*)(y + c);
        float yv[4] = {v.x, v.y, v.z, v.w};
#pragma unroll
        for (int j = 0; j < 4; j++)
#pragma unroll
            for (int a = 0; a < ADIM; a++)
                acc[a] = fmaf(yv[j], ws[(c + j) * ADIM + a], acc[a]);
    }
    float* qp = q + row * ADIM;
#pragma unroll
    for (int a = 0; a < ADIM; a++) qp[a] = acc[a];
}

// ---------------- launch ----------------
extern "C" void kernel_launch(void* const* d_in, const int* in_sizes, int n_in,
                              void* d_out, int out_size)
{
    const float* hidden    = (const float*)d_in[0];
    const float* obs       = (const float*)d_in[1];
    const int*   dones     = (const int*)d_in[2];
    const int*   last_acts = (const int*)d_in[3];
    const float* w0   = (const float*)d_in[4];
    const float* b0   = (const float*)d_in[5];
    const float* ln0s = (const float*)d_in[6];
    const float* ln0b = (const float*)d_in[7];
    const float* w1   = (const float*)d_in[8];
    const float* b1   = (const float*)d_in[9];
    const float* ln1s = (const float*)d_in[10];
    const float* ln1b = (const float*)d_in[11];
    const float* w_ir = (const float*)d_in[12];
    const float* b_ir = (const float*)d_in[13];
    const float* w_iz = (const float*)d_in[14];
    const float* b_iz = (const float*)d_in[15];
    const float* w_in = (const float*)d_in[16];
    const float* b_in = (const float*)d_in[17];
    const float* w_hr = (const float*)d_in[18];
    const float* w_hz = (const float*)d_in[19];
    const float* w_hn = (const float*)d_in[20];
    const float* b_hn = (const float*)d_in[21];
    const float* w_out = (const float*)d_in[22];
    const float* b_out = (const float*)d_in[23];

    float* out_hidden = (float*)d_out;
    float* out_q      = (float*)d_out + (size_t)BATCH * HID;

    float *S0, *S1, *Xg, *w0c, *w1c, *wgc;
    cudaGetSymbolAddress((void**)&S0,  g_S0);
    cudaGetSymbolAddress((void**)&S1,  g_S1);
    cudaGetSymbolAddress((void**)&Xg,  g_Xg);
    cudaGetSymbolAddress((void**)&w0c, g_w0c);
    cudaGetSymbolAddress((void**)&w1c, g_w1c);
    cudaGetSymbolAddress((void**)&wgc, g_wgc);

    const int gemm_smem = 3 * (GA_SZ + GB_SZ) * 4;                              // 105984 B
    const int scan_smem = (3 * 512 * WP_LD + 8 * ST_WARP + 64) * 4;             // 203008 B
    cudaFuncSetAttribute(gemm_db, cudaFuncAttributeMaxDynamicSharedMemorySize, gemm_smem);
    cudaFuncSetAttribute(scan_kernel, cudaFuncAttributeMaxDynamicSharedMemorySize, scan_smem);

    conv_tf32<<<(ROWS * HID / 4 + 255) / 256, 256>>>(obs, S1, ROWS * HID / 4);
    conv_tf32<<<256, 256>>>(w0, w0c, HID * HID / 4);
    conv_gates<<<1024, 256>>>(w_ir, w_iz, w_in, wgc);
    gemm_db<<<dim3(4, 512), 128, gemm_smem>>>(S1, w0c, S0, HID, HID);     // L0
    conv_tf32<<<256, 256>>>(w1, w1c, HID * HID / 4);
    mask0_kernel<<<(BATCH * HID) / 256, 256>>>(hidden, dones);
    ln_relu_kernel<<<ROWS, 128>>>(S0, S1, b0, ln0s, ln0b, w0, last_acts);
    gemm_db<<<dim3(4, 512), 128, gemm_smem>>>(S1, w1c, S0, HID, HID);     // L1
    ln_relu_kernel<<<ROWS, 128>>>(S0, S1, b1, ln1s, ln1b, nullptr, nullptr);
    gemm_db<<<dim3(12, 512), 128, gemm_smem>>>(S1, wgc, Xg, NG3, HID);    // gates

    scan_kernel<<<SC_CTAS, 256, scan_smem>>>(w_hr, w_hz, w_hn,
                                             b_ir, b_iz, b_in, b_hn,
                                             dones, out_hidden);

    qout_kernel<<<ROWS / 256, 256>>>(w_out, b_out, out_q);
}